// round 3
// baseline (speedup 1.0000x reference)
#include <cuda_runtime.h>
#include <math.h>

#define N_ATOMS 50000
#define N_EDGES 100000
#define B_G 50
#define M_M 50
#define NPG 1000
#define DIN 32
#define H1D 32
#define H2D 64
#define DE 16
#define AAF 95
#define G_DIM 128
#define K_S 3
#define T_L 6
#define EA 98
#define F1D 64
#define F2D 32
#define F3D 16
#define X0DIM 159
#define YSTRIDE 576   /* 18 * 32 */

typedef unsigned long long u64;

// ---------------- f32x2 helpers ----------------
__device__ __forceinline__ u64 pk2(float a, float b) {
    u64 r;
    asm("mov.b64 %0, {%1, %2};" : "=l"(r) : "f"(a), "f"(b));
    return r;
}
__device__ __forceinline__ void fma2(u64& d, u64 a, u64 b) {
    asm("fma.rn.f32x2 %0, %1, %2, %3;" : "=l"(d) : "l"(a), "l"(b), "l"(d));
}
__device__ __forceinline__ void add2(u64& d, u64 a) {
    asm("add.rn.f32x2 %0, %1, %2;" : "=l"(d) : "l"(a), "l"(d));
}
__device__ __forceinline__ float2 up2(u64 v) {
    float2 f;
    asm("mov.b64 {%0, %1}, %2;" : "=f"(f.x), "=f"(f.y) : "l"(v));
    return f;
}
__device__ __forceinline__ void red1(float* p, float a) {
    asm volatile("red.global.add.f32 [%0], %1;" :: "l"(p), "f"(a) : "memory");
}
__device__ __forceinline__ void red4(float* p, float a, float b, float c, float d) {
    asm volatile("red.global.add.v4.f32 [%0], {%1, %2, %3, %4};"
                 :: "l"(p), "f"(a), "f"(b), "f"(c), "f"(d) : "memory");
}

// ---------------- scratch ----------------
__device__ float g_y[(size_t)N_ATOMS * YSTRIDE];   // 115.2 MB node pre-contraction
__device__ float g_h1[N_ATOMS * H1D];
__device__ float g_h2[N_ATOMS * H2D];
__device__ float g_aa[B_G * M_M * H2D];
__device__ float g_gg[B_G * M_M * G_DIM];
__device__ int   g_aoff[M_M + 1];
__device__ int   g_asrc[EA];
__device__ float g_anorm[EA];

// ---------------- amino graph prep ----------------
__global__ void k_amino_prep(const int* __restrict__ aei) {
    if (threadIdx.x != 0 || blockIdx.x != 0) return;
    int deg[M_M]; float dinv[M_M]; int off[M_M + 1]; int cnt[M_M];
    for (int m = 0; m < M_M; ++m) { deg[m] = 0; cnt[m] = 0; }
    for (int e = 0; e < EA; ++e) deg[aei[EA + e]]++;
    for (int m = 0; m < M_M; ++m)
        dinv[m] = (deg[m] > 0) ? (1.0f / sqrtf((float)deg[m])) : 0.0f;
    off[0] = 0;
    for (int m = 0; m < M_M; ++m) off[m + 1] = off[m] + deg[m];
    for (int e = 0; e < EA; ++e) {
        int s = aei[e], d = aei[EA + e];
        int slot = off[d] + cnt[d]++;
        g_asrc[slot] = s;
        g_anorm[slot] = dinv[s] * dinv[d];
    }
    for (int m = 0; m <= M_M; ++m) g_aoff[m] = off[m];
}

// ---------------- node GEMM: y[n,d,o32] = h[n,:] @ Waug[d]  (d=16: bias-mat, d=17: root -> h out) ----------------
// smem: sW[18*1024] weights, sW[18432..18463] output bias
// warp handles 8 nodes x 4 lanes; lane computes 8 outputs (q = lane&3).
__global__ void __launch_bounds__(256) k_ygemm(const float* __restrict__ xin,
                                               int hin_sel, int relu,
                                               const float* __restrict__ We,
                                               const float* __restrict__ be,
                                               const float* __restrict__ root,
                                               const float* __restrict__ bias,
                                               int o_total, int o_base,
                                               int which_h, int h_stride) {
    extern __shared__ float sW[];
    int tid = threadIdx.x;
    for (int i = tid; i < 18 * 1024; i += 256) {
        int d = i >> 10, r = i & 1023, f = r >> 5, o = r & 31;
        float v;
        if (d < 16)       v = We[(d * 32 + f) * o_total + o_base + o];
        else if (d == 16) v = be[f * o_total + o_base + o];
        else              v = root[f * o_total + o_base + o];
        sW[i] = v;
    }
    if (tid < 32) sW[18 * 1024 + tid] = bias[o_base + tid];
    __syncthreads();

    const float* hin = hin_sel ? g_h1 : xin;
    int lane = tid & 31;
    int warp = tid >> 5;
    int q = lane & 3;
    int node = blockIdx.x * 64 + warp * 8 + (lane >> 2);
    bool valid = node < N_ATOMS;

    float hv[32];
    if (valid) {
        const float4* hp = (const float4*)(hin + (size_t)node * 32);
#pragma unroll
        for (int j = 0; j < 8; ++j) {
            float4 v = hp[j];
            if (relu) {
                v.x = fmaxf(v.x, 0.0f); v.y = fmaxf(v.y, 0.0f);
                v.z = fmaxf(v.z, 0.0f); v.w = fmaxf(v.w, 0.0f);
            }
            hv[j * 4 + 0] = v.x; hv[j * 4 + 1] = v.y;
            hv[j * 4 + 2] = v.z; hv[j * 4 + 3] = v.w;
        }
    } else {
#pragma unroll
        for (int j = 0; j < 32; ++j) hv[j] = 0.0f;
    }

    float* yrow = g_y + (size_t)node * YSTRIDE;
    float* hdst = (which_h == 1 ? g_h1 : g_h2) + (size_t)node * h_stride + o_base;

#pragma unroll 1
    for (int d = 0; d < 18; ++d) {
        u64 a0 = 0ull, a1 = 0ull, a2 = 0ull, a3 = 0ull;
        const float* wdb = sW + d * 1024 + q * 8;
#pragma unroll
        for (int f = 0; f < 32; ++f) {
            u64 x2 = pk2(hv[f], hv[f]);
            const ulonglong2 w0 = *(const ulonglong2*)(wdb + f * 32);
            const ulonglong2 w1 = *(const ulonglong2*)(wdb + f * 32 + 4);
            fma2(a0, x2, w0.x); fma2(a1, x2, w0.y);
            fma2(a2, x2, w1.x); fma2(a3, x2, w1.y);
        }
        if (valid) {
            if (d < 17) {
                ulonglong2 s0; s0.x = a0; s0.y = a1;
                ulonglong2 s1; s1.x = a2; s1.y = a3;
                *(ulonglong2*)(yrow + d * 32 + q * 8) = s0;
                *(ulonglong2*)(yrow + d * 32 + q * 8 + 4) = s1;
            } else {
                float2 p0 = up2(a0), p1 = up2(a1), p2 = up2(a2), p3 = up2(a3);
                const float* bb = sW + 18 * 1024 + q * 8;
                float4 r0 = make_float4(p0.x + bb[0], p0.y + bb[1],
                                        p1.x + bb[2], p1.y + bb[3]);
                float4 r1 = make_float4(p2.x + bb[4], p2.y + bb[5],
                                        p3.x + bb[6], p3.y + bb[7]);
                *(float4*)(hdst + q * 8) = r0;
                *(float4*)(hdst + q * 8 + 4) = r1;
            }
        }
    }
}

// ---------------- edge contraction: msg[e,o] = sum_d ea'_d * y[src,d,o]; red-add to h[dst] ----------------
__global__ void __launch_bounds__(256) k_econ(const int* __restrict__ eidx,
                                              const float* __restrict__ ea_g,
                                              int which_h, int h_stride, int o_base) {
    int warp = threadIdx.x >> 5, lane = threadIdx.x & 31;
    int e = blockIdx.x * 8 + warp;
    int src = eidx[e];
    int dst = eidx[N_EDGES + e];
    float ead = (lane < 16) ? ea_g[e * 16 + lane] : 1.0f;
    const float* yrow = g_y + (size_t)src * YSTRIDE + lane;
    float acc = 0.0f;
#pragma unroll
    for (int d = 0; d < 17; ++d) {
        float w = __shfl_sync(0xffffffffu, ead, d);
        acc = fmaf(w, yrow[d * 32], acc);
    }
    float* hp = (which_h == 1 ? g_h1 : g_h2) + (size_t)dst * h_stride + o_base + lane;
    red1(hp, acc);
}

// ---------------- atom attention readout -> g_aa; also zeroes g_gg ----------------
__global__ void __launch_bounds__(128) k_attn(const int* __restrict__ labels,
                                              const float* __restrict__ wa_g,
                                              const float* __restrict__ ba_g) {
    extern __shared__ float sm[];
    float* sc = sm;
    float* wa = sm + 1000;
    float* red = sm + 1064;
    float* wacc = sm + 1192;

    int b = blockIdx.x, tid = threadIdx.x;
    const float* h2b = g_h2 + (size_t)b * NPG * H2D;
    if (tid < 64) wa[tid] = wa_g[tid];
    for (int i = tid; i < 4 * M_M * H2D; i += 128) wacc[i] = 0.0f;
    for (int i = tid; i < M_M * G_DIM; i += 128) g_gg[b * M_M * G_DIM + i] = 0.0f;
    __syncthreads();

    float ba = ba_g[0];
    for (int i = tid; i < NPG; i += 128) {
        const float4* r4 = (const float4*)(h2b + i * H2D);
        float s = ba;
#pragma unroll
        for (int o4 = 0; o4 < 16; ++o4) {
            float4 v = r4[o4];
            s = fmaf(fmaxf(v.x, 0.0f), wa[o4 * 4 + 0], s);
            s = fmaf(fmaxf(v.y, 0.0f), wa[o4 * 4 + 1], s);
            s = fmaf(fmaxf(v.z, 0.0f), wa[o4 * 4 + 2], s);
            s = fmaf(fmaxf(v.w, 0.0f), wa[o4 * 4 + 3], s);
        }
        sc[i] = s;
    }
    __syncthreads();
    float mx = -1e30f;
    for (int i = tid; i < NPG; i += 128) mx = fmaxf(mx, sc[i]);
    red[tid] = mx;
    __syncthreads();
    for (int s = 64; s > 0; s >>= 1) {
        if (tid < s) red[tid] = fmaxf(red[tid], red[tid + s]);
        __syncthreads();
    }
    mx = red[0];
    __syncthreads();
    float se = 0.0f;
    for (int i = tid; i < NPG; i += 128) {
        float e2 = expf(sc[i] - mx);
        sc[i] = e2;
        se += e2;
    }
    red[tid] = se;
    __syncthreads();
    for (int s = 64; s > 0; s >>= 1) {
        if (tid < s) red[tid] += red[tid + s];
        __syncthreads();
    }
    float inv = 1.0f / red[0];
    __syncthreads();

    int w = tid >> 5, lane = tid & 31;
    float* wp = wacc + w * (M_M * H2D);
    for (int i = w; i < NPG; i += 4) {
        int m = labels[b * NPG + i];
        float c = sc[i] * inv;
        const float* row = h2b + i * H2D;
        wp[m * H2D + lane]      += c * fmaxf(row[lane], 0.0f);
        wp[m * H2D + 32 + lane] += c * fmaxf(row[32 + lane], 0.0f);
    }
    __syncthreads();
    for (int i = tid; i < M_M * H2D; i += 128) {
        g_aa[b * M_M * H2D + i] =
            wacc[i] + wacc[3200 + i] + wacc[6400 + i] + wacc[9600 + i];
    }
}

// ---------------- ARMA (smem-staged weights, f32x2) ----------------
__device__ __forceinline__ void arma_mm2(u64 acc2[5][2], const float* __restrict__ xs,
                                         int xstride, int Fdim,
                                         const float* __restrict__ ws, int m0, int o0) {
    const float* x0p = xs + m0 * xstride;
    const float* x1p = x0p + xstride;
    const float* x2p = x1p + xstride;
    const float* x3p = x2p + xstride;
    const float* x4p = x3p + xstride;
    const float* wp = ws + o0;
#pragma unroll 4
    for (int f = 0; f < Fdim; ++f) {
        ulonglong2 wv = *(const ulonglong2*)(wp + f * G_DIM);
        u64 x0 = pk2(x0p[f], x0p[f]);
        fma2(acc2[0][0], x0, wv.x); fma2(acc2[0][1], x0, wv.y);
        u64 x1 = pk2(x1p[f], x1p[f]);
        fma2(acc2[1][0], x1, wv.x); fma2(acc2[1][1], x1, wv.y);
        u64 x2 = pk2(x2p[f], x2p[f]);
        fma2(acc2[2][0], x2, wv.x); fma2(acc2[2][1], x2, wv.y);
        u64 x3 = pk2(x3p[f], x3p[f]);
        fma2(acc2[3][0], x3, wv.x); fma2(acc2[3][1], x3, wv.y);
        u64 x4 = pk2(x4p[f], x4p[f]);
        fma2(acc2[4][0], x4, wv.x); fma2(acc2[4][1], x4, wv.y);
    }
}

__device__ __forceinline__ void stage_w(float* dstS, const float* __restrict__ src,
                                        int n4, int tid) {
    const float4* s4 = (const float4*)src;
    float4* d4 = (float4*)dstS;
    for (int i = tid; i < n4; i += 320) d4[i] = s4[i];
}

// smem floats: x0s[8000] | bufA[6400] | bufB[6400] | ws[20352] (at 20800)
__global__ void __launch_bounds__(320) k_arma(const float* __restrict__ aaf,
                                              const float* __restrict__ w_init,
                                              const float* __restrict__ w_mid,
                                              const float* __restrict__ w_root,
                                              const float* __restrict__ w_bias) {
    extern __shared__ float sm[];
    float* x0s = sm;
    float* bufA = sm + 8000;
    float* bufB = sm + 14400;
    float* ws = sm + 20800;

    int b = blockIdx.x / K_S, k = blockIdx.x % K_S;
    int tid = threadIdx.x;
    for (int i = tid; i < M_M * X0DIM; i += 320) {
        int m = i / X0DIM, f = i % X0DIM;
        float v = (f < H2D) ? g_aa[(b * M_M + m) * H2D + f]
                            : aaf[(b * M_M + m) * AAF + (f - H2D)];
        x0s[m * 160 + f] = v;
    }
    stage_w(ws, w_init + (size_t)k * X0DIM * G_DIM, X0DIM * G_DIM / 4, tid);
    __syncthreads();

    int warp = tid >> 5, lane = tid & 31;
    int m0 = warp * 5, o0 = lane * 4;
    u64 acc2[5][2];

#pragma unroll
    for (int mi = 0; mi < 5; ++mi) { acc2[mi][0] = 0ull; acc2[mi][1] = 0ull; }
    arma_mm2(acc2, x0s, 160, X0DIM, ws, m0, o0);
#pragma unroll
    for (int mi = 0; mi < 5; ++mi) {
        ulonglong2 v; v.x = acc2[mi][0]; v.y = acc2[mi][1];
        *(ulonglong2*)(bufA + (m0 + mi) * G_DIM + o0) = v;
    }
    __syncthreads();  // bufA visible; ws free for re-stage

    float accf[5][4];
    for (int t = 0; t < T_L; ++t) {
        const float* cur = bufA;
        if (t > 0) {
            stage_w(ws, w_mid + (size_t)((t - 1) * K_S + k) * G_DIM * G_DIM,
                    G_DIM * G_DIM / 4, tid);
            __syncthreads();
#pragma unroll
            for (int mi = 0; mi < 5; ++mi) { acc2[mi][0] = 0ull; acc2[mi][1] = 0ull; }
            arma_mm2(acc2, bufA, G_DIM, G_DIM, ws, m0, o0);
#pragma unroll
            for (int mi = 0; mi < 5; ++mi) {
                ulonglong2 v; v.x = acc2[mi][0]; v.y = acc2[mi][1];
                *(ulonglong2*)(bufB + (m0 + mi) * G_DIM + o0) = v;
            }
            __syncthreads();  // ws reads done + bufB visible
            cur = bufB;
        }
        stage_w(ws, w_root + (size_t)(t * K_S + k) * X0DIM * G_DIM,
                X0DIM * G_DIM / 4, tid);
        __syncthreads();
#pragma unroll
        for (int mi = 0; mi < 5; ++mi) { acc2[mi][0] = 0ull; acc2[mi][1] = 0ull; }
        arma_mm2(acc2, x0s, 160, X0DIM, ws, m0, o0);
#pragma unroll
        for (int mi = 0; mi < 5; ++mi) {
            int m = m0 + mi;
            int e0 = g_aoff[m], e1 = g_aoff[m + 1];
            for (int e = e0; e < e1; ++e) {
                int s = g_asrc[e];
                u64 nr2 = pk2(g_anorm[e], g_anorm[e]);
                ulonglong2 cv = *(const ulonglong2*)(cur + s * G_DIM + o0);
                fma2(acc2[mi][0], nr2, cv.x);
                fma2(acc2[mi][1], nr2, cv.y);
            }
        }
        ulonglong2 bv = *(const ulonglong2*)(w_bias + (t * K_S + k) * G_DIM + o0);
#pragma unroll
        for (int mi = 0; mi < 5; ++mi) {
            add2(acc2[mi][0], bv.x);
            add2(acc2[mi][1], bv.y);
            float2 lo = up2(acc2[mi][0]), hi = up2(acc2[mi][1]);
            accf[mi][0] = fmaxf(lo.x, 0.0f); accf[mi][1] = fmaxf(lo.y, 0.0f);
            accf[mi][2] = fmaxf(hi.x, 0.0f); accf[mi][3] = fmaxf(hi.y, 0.0f);
        }
        __syncthreads();  // prop reads of cur complete before overwriting bufA
#pragma unroll
        for (int mi = 0; mi < 5; ++mi)
            *(float4*)(bufA + (m0 + mi) * G_DIM + o0) =
                make_float4(accf[mi][0], accf[mi][1], accf[mi][2], accf[mi][3]);
        __syncthreads();
    }
    const float invK = 1.0f / (float)K_S;
#pragma unroll
    for (int mi = 0; mi < 5; ++mi)
        red4(&g_gg[b * M_M * G_DIM + (m0 + mi) * G_DIM + o0],
             accf[mi][0] * invK, accf[mi][1] * invK,
             accf[mi][2] * invK, accf[mi][3] * invK);
}

// ---------------- amino attention + MLP head ----------------
__global__ void __launch_bounds__(128) k_final(const float* __restrict__ waa,
                                               const float* __restrict__ baa,
                                               const float* __restrict__ W1,
                                               const float* __restrict__ b1,
                                               const float* __restrict__ W2,
                                               const float* __restrict__ b2,
                                               const float* __restrict__ W3,
                                               const float* __restrict__ b3,
                                               const float* __restrict__ W4,
                                               const float* __restrict__ b4,
                                               float* __restrict__ out) {
    __shared__ float gs[M_M * G_DIM];
    __shared__ float sc[M_M];
    __shared__ float p[G_DIM];
    __shared__ float f1[F1D];
    __shared__ float f2[F2D];
    __shared__ float f3[F3D];
    int b = blockIdx.x, tid = threadIdx.x;
    for (int i = tid; i < M_M * G_DIM; i += 128) gs[i] = g_gg[b * M_M * G_DIM + i];
    __syncthreads();
    if (tid < M_M) {
        float s = baa[0];
#pragma unroll 4
        for (int o = 0; o < G_DIM; ++o) s = fmaf(gs[tid * G_DIM + o], waa[o], s);
        sc[tid] = s;
    }
    __syncthreads();
    if (tid == 0) {
        float mx = -1e30f;
        for (int m = 0; m < M_M; ++m) mx = fmaxf(mx, sc[m]);
        float se = 0.0f;
        for (int m = 0; m < M_M; ++m) {
            float e = expf(sc[m] - mx);
            sc[m] = e;
            se += e;
        }
        float inv = 1.0f / se;
        for (int m = 0; m < M_M; ++m) sc[m] *= inv;
    }
    __syncthreads();
    {
        float pv = 0.0f;
        for (int m = 0; m < M_M; ++m) pv = fmaf(sc[m], gs[m * G_DIM + tid], pv);
        p[tid] = pv;
    }
    __syncthreads();
    if (tid < F1D) {
        float v = b1[tid];
        for (int i = 0; i < G_DIM; ++i) v = fmaf(p[i], W1[i * F1D + tid], v);
        f1[tid] = fmaxf(v, 0.0f);
    }
    __syncthreads();
    if (tid < F2D) {
        float v = b2[tid];
        for (int i = 0; i < F1D; ++i) v = fmaf(f1[i], W2[i * F2D + tid], v);
        f2[tid] = fmaxf(v, 0.0f);
    }
    __syncthreads();
    if (tid < F3D) {
        float v = b3[tid];
        for (int i = 0; i < F2D; ++i) v = fmaf(f2[i], W3[i * F3D + tid], v);
        f3[tid] = fmaxf(v, 0.0f);
    }
    __syncthreads();
    if (tid == 0) {
        float v = b4[0];
        for (int i = 0; i < F3D; ++i) v = fmaf(f3[i], W4[i], v);
        out[b] = v;
    }
}

// ---------------- launch ----------------
extern "C" void kernel_launch(void* const* d_in, const int* in_sizes, int n_in,
                              void* d_out, int out_size) {
    const float* x              = (const float*)d_in[0];
    const float* edge_attr      = (const float*)d_in[1];
    const float* aa_features    = (const float*)d_in[2];
    const int*   edge_index     = (const int*)d_in[3];
    const int*   monomer_labels = (const int*)d_in[4];
    const int*   amino_edge_idx = (const int*)d_in[5];
    const float* W_e1   = (const float*)d_in[6];
    const float* b_e1   = (const float*)d_in[7];
    const float* root1  = (const float*)d_in[8];
    const float* bias1  = (const float*)d_in[9];
    const float* W_e2   = (const float*)d_in[10];
    const float* b_e2   = (const float*)d_in[11];
    const float* root2  = (const float*)d_in[12];
    const float* bias2  = (const float*)d_in[13];
    const float* Wa_atom = (const float*)d_in[14];
    const float* ba_atom = (const float*)d_in[15];
    const float* arma_init_w = (const float*)d_in[16];
    const float* arma_w      = (const float*)d_in[17];
    const float* arma_root_w = (const float*)d_in[18];
    const float* arma_bias   = (const float*)d_in[19];
    const float* Wa_aa = (const float*)d_in[20];
    const float* ba_aa = (const float*)d_in[21];
    const float* W1 = (const float*)d_in[22];
    const float* b1 = (const float*)d_in[23];
    const float* W2 = (const float*)d_in[24];
    const float* b2 = (const float*)d_in[25];
    const float* W3 = (const float*)d_in[26];
    const float* b3 = (const float*)d_in[27];
    const float* W4 = (const float*)d_in[28];
    const float* b4 = (const float*)d_in[29];
    float* out = (float*)d_out;

    const int YG_SMEM   = (18 * 1024 + 32) * 4;              // 73856 B
    const int ATTN_SMEM = (1000 + 64 + 128 + 12800) * 4;     // 55968 B
    const int ARMA_SMEM = (20800 + 20352) * 4;               // 164608 B
    cudaFuncSetAttribute(k_ygemm, cudaFuncAttributeMaxDynamicSharedMemorySize, YG_SMEM);
    cudaFuncSetAttribute(k_attn, cudaFuncAttributeMaxDynamicSharedMemorySize, ATTN_SMEM);
    cudaFuncSetAttribute(k_arma, cudaFuncAttributeMaxDynamicSharedMemorySize, ARMA_SMEM);

    const int GEMM_GRID = (N_ATOMS + 63) / 64;   // 782
    const int ECON_GRID = N_EDGES / 8;           // 12500

    k_amino_prep<<<1, 32>>>(amino_edge_idx);

    // conv1: y = x @ Waug1  (h1 root+bias written by d=17), then edge contraction
    k_ygemm<<<GEMM_GRID, 256, YG_SMEM>>>(x, 0, 0, W_e1, b_e1, root1, bias1, 32, 0, 1, H1D);
    k_econ<<<ECON_GRID, 256>>>(edge_index, edge_attr, 1, H1D, 0);

    // conv2 half 0 (outputs 0..31)
    k_ygemm<<<GEMM_GRID, 256, YG_SMEM>>>(x, 1, 1, W_e2, b_e2, root2, bias2, 64, 0, 2, H2D);
    k_econ<<<ECON_GRID, 256>>>(edge_index, edge_attr, 2, H2D, 0);

    // conv2 half 1 (outputs 32..63)
    k_ygemm<<<GEMM_GRID, 256, YG_SMEM>>>(x, 1, 1, W_e2, b_e2, root2, bias2, 64, 32, 2, H2D);
    k_econ<<<ECON_GRID, 256>>>(edge_index, edge_attr, 2, H2D, 32);

    k_attn<<<B_G, 128, ATTN_SMEM>>>(monomer_labels, Wa_atom, ba_atom);
    k_arma<<<B_G * K_S, 320, ARMA_SMEM>>>(aa_features, arma_init_w, arma_w, arma_root_w, arma_bias);
    k_final<<<B_G, 128>>>(Wa_aa, ba_aa, W1, b1, W2, b2, W3, b3, W4, b4, out);
}

// round 4
// speedup vs baseline: 1.5290x; 1.5290x over previous
#include <cuda_runtime.h>
#include <math.h>

#define N_ATOMS 50000
#define N_EDGES 100000
#define B_G 50
#define M_M 50
#define NPG 1000
#define DIN 32
#define H1D 32
#define H2D 64
#define DE 16
#define AAF 95
#define G_DIM 128
#define K_S 3
#define T_L 6
#define EA 98
#define F1D 64
#define F2D 32
#define F3D 16
#define X0DIM 159
#define YSTRIDE 576   /* 18 * 32 */

typedef unsigned long long u64;

// ---------------- f32x2 helpers ----------------
__device__ __forceinline__ u64 pk2(float a, float b) {
    u64 r;
    asm("mov.b64 %0, {%1, %2};" : "=l"(r) : "f"(a), "f"(b));
    return r;
}
__device__ __forceinline__ void fma2(u64& d, u64 a, u64 b) {
    asm("fma.rn.f32x2 %0, %1, %2, %3;" : "=l"(d) : "l"(a), "l"(b), "l"(d));
}
__device__ __forceinline__ void add2(u64& d, u64 a) {
    asm("add.rn.f32x2 %0, %1, %2;" : "=l"(d) : "l"(a), "l"(d));
}
__device__ __forceinline__ float2 up2(u64 v) {
    float2 f;
    asm("mov.b64 {%0, %1}, %2;" : "=f"(f.x), "=f"(f.y) : "l"(v));
    return f;
}
__device__ __forceinline__ void red1(float* p, float a) {
    asm volatile("red.global.add.f32 [%0], %1;" :: "l"(p), "f"(a) : "memory");
}
__device__ __forceinline__ void red4(float* p, float a, float b, float c, float d) {
    asm volatile("red.global.add.v4.f32 [%0], {%1, %2, %3, %4};"
                 :: "l"(p), "f"(a), "f"(b), "f"(c), "f"(d) : "memory");
}

// ---------------- scratch ----------------
__device__ float g_y[(size_t)N_ATOMS * YSTRIDE];   // 115.2 MB node pre-contraction
__device__ float g_h1[N_ATOMS * H1D];
__device__ float g_h2[N_ATOMS * H2D];
__device__ float g_aa[B_G * M_M * H2D];
__device__ float g_gg[B_G * M_M * G_DIM];
__device__ int   g_aoff[M_M + 1];
__device__ int   g_asrc[EA];
__device__ float g_anorm[EA];

// ---------------- amino graph prep ----------------
__global__ void k_amino_prep(const int* __restrict__ aei) {
    if (threadIdx.x != 0 || blockIdx.x != 0) return;
    int deg[M_M]; float dinv[M_M]; int off[M_M + 1]; int cnt[M_M];
    for (int m = 0; m < M_M; ++m) { deg[m] = 0; cnt[m] = 0; }
    for (int e = 0; e < EA; ++e) deg[aei[EA + e]]++;
    for (int m = 0; m < M_M; ++m)
        dinv[m] = (deg[m] > 0) ? (1.0f / sqrtf((float)deg[m])) : 0.0f;
    off[0] = 0;
    for (int m = 0; m < M_M; ++m) off[m + 1] = off[m] + deg[m];
    for (int e = 0; e < EA; ++e) {
        int s = aei[e], d = aei[EA + e];
        int slot = off[d] + cnt[d]++;
        g_asrc[slot] = s;
        g_anorm[slot] = dinv[s] * dinv[d];
    }
    for (int m = 0; m <= M_M; ++m) g_aoff[m] = off[m];
}

// ---------------- node GEMM (register-tiled): y[n, 576] = h[n,:] @ Waug ----------------
// 576 cols = 18 d-slices of 32. d<16: W_e slice; d=16: edge-bias matrix; d=17: root (+bias) -> h out.
// Block: 256 nodes x 64 cols; thread: 8 nodes x 8 cols. grid = (196, 9).
// smem: sh[32][256] (h transposed), sw[32][64], sb[32]
__global__ void __launch_bounds__(256, 2) k_ygemm(const float* __restrict__ xin,
                                                  int hin_sel, int relu,
                                                  const float* __restrict__ We,
                                                  const float* __restrict__ be,
                                                  const float* __restrict__ root,
                                                  const float* __restrict__ bias,
                                                  int o_total, int o_base,
                                                  int which_h, int h_stride) {
    extern __shared__ float sm_[];
    float* sh = sm_;              // 8192: [f][n] f=0..31, n=0..255
    float* sw = sm_ + 8192;       // 2048: [f][cc] cc=0..63
    float* sb = sm_ + 8192 + 2048;

    int tid = threadIdx.x;
    int n0 = blockIdx.x * 256;
    int ct = blockIdx.y;          // col tile 0..8

    const float* hin = hin_sel ? g_h1 : xin;

    // stage h transposed: iteration it covers nodes it*32..+32, all 8 float4-chunks
    int lane = tid & 31, wrp = tid >> 5;
#pragma unroll
    for (int it = 0; it < 8; ++it) {
        int n = it * 32 + lane;       // 0..255
        int fq = wrp;                 // 0..7
        int gn = n0 + n;
        float4 v = make_float4(0.f, 0.f, 0.f, 0.f);
        if (gn < N_ATOMS) v = *(const float4*)(hin + (size_t)gn * 32 + fq * 4);
        if (relu) {
            v.x = fmaxf(v.x, 0.f); v.y = fmaxf(v.y, 0.f);
            v.z = fmaxf(v.z, 0.f); v.w = fmaxf(v.w, 0.f);
        }
        sh[(fq * 4 + 0) * 256 + n] = v.x;
        sh[(fq * 4 + 1) * 256 + n] = v.y;
        sh[(fq * 4 + 2) * 256 + n] = v.z;
        sh[(fq * 4 + 3) * 256 + n] = v.w;
    }
    // stage weights for this col tile
    for (int i = tid; i < 32 * 64; i += 256) {
        int f = i >> 6, cc = i & 63;
        int c = ct * 64 + cc;
        int d = c >> 5, o = c & 31;
        float v;
        if (d < 16)       v = We[(d * 32 + f) * o_total + o_base + o];
        else if (d == 16) v = be[f * o_total + o_base + o];
        else              v = root[f * o_total + o_base + o];
        sw[f * 64 + cc] = v;
    }
    if (tid < 32) sb[tid] = bias[o_base + tid];
    __syncthreads();

    int tx = tid & 7;             // col group: 8 cols
    int ty = tid >> 3;            // row group: 8 nodes (0..31)
    const float* shp = sh + ty * 8;
    const float* swp = sw + tx * 8;

    u64 acc[8][4];
#pragma unroll
    for (int r = 0; r < 8; ++r)
#pragma unroll
        for (int j = 0; j < 4; ++j) acc[r][j] = 0ull;

#pragma unroll 4
    for (int f = 0; f < 32; ++f) {
        float4 hA = *(const float4*)(shp + f * 256);
        float4 hB = *(const float4*)(shp + f * 256 + 4);
        ulonglong2 w0 = *(const ulonglong2*)(swp + f * 64);
        ulonglong2 w1 = *(const ulonglong2*)(swp + f * 64 + 4);
        float hr[8] = {hA.x, hA.y, hA.z, hA.w, hB.x, hB.y, hB.z, hB.w};
#pragma unroll
        for (int r = 0; r < 8; ++r) {
            u64 p = pk2(hr[r], hr[r]);
            fma2(acc[r][0], p, w0.x);
            fma2(acc[r][1], p, w0.y);
            fma2(acc[r][2], p, w1.x);
            fma2(acc[r][3], p, w1.y);
        }
    }

    int c0 = ct * 64 + tx * 8;
    int d = c0 >> 5, o0 = c0 & 31;
    int nb = n0 + ty * 8;
    if (d < 17) {
#pragma unroll
        for (int r = 0; r < 8; ++r) {
            int n = nb + r;
            if (n >= N_ATOMS) break;
            float* yp = g_y + (size_t)n * YSTRIDE + d * 32 + o0;
            float2 p0 = up2(acc[r][0]), p1 = up2(acc[r][1]);
            float2 p2 = up2(acc[r][2]), p3 = up2(acc[r][3]);
            *(float4*)(yp)     = make_float4(p0.x, p0.y, p1.x, p1.y);
            *(float4*)(yp + 4) = make_float4(p2.x, p2.y, p3.x, p3.y);
        }
    } else {
        float* hbase = (which_h == 1 ? g_h1 : g_h2);
        float b0 = sb[o0 + 0], b1 = sb[o0 + 1], b2 = sb[o0 + 2], b3 = sb[o0 + 3];
        float b4 = sb[o0 + 4], b5 = sb[o0 + 5], b6 = sb[o0 + 6], b7 = sb[o0 + 7];
#pragma unroll
        for (int r = 0; r < 8; ++r) {
            int n = nb + r;
            if (n >= N_ATOMS) break;
            float* hp = hbase + (size_t)n * h_stride + o_base + o0;
            float2 p0 = up2(acc[r][0]), p1 = up2(acc[r][1]);
            float2 p2 = up2(acc[r][2]), p3 = up2(acc[r][3]);
            *(float4*)(hp)     = make_float4(p0.x + b0, p0.y + b1, p1.x + b2, p1.y + b3);
            *(float4*)(hp + 4) = make_float4(p2.x + b4, p2.y + b5, p3.x + b6, p3.y + b7);
        }
    }
}

// ---------------- edge contraction: msg[e,o] = sum_d ea'_d * y[src,d,o]; red-add to h[dst] ----------------
__global__ void __launch_bounds__(256) k_econ(const int* __restrict__ eidx,
                                              const float* __restrict__ ea_g,
                                              int which_h, int h_stride, int o_base) {
    int warp = threadIdx.x >> 5, lane = threadIdx.x & 31;
    int e = blockIdx.x * 8 + warp;
    int src = __ldg(eidx + e);
    int dst = __ldg(eidx + N_EDGES + e);
    float ead = (lane < 16) ? __ldg(ea_g + e * 16 + lane) : 1.0f;
    const float* yrow = g_y + (size_t)src * YSTRIDE + lane;
    float acc = 0.0f;
#pragma unroll
    for (int d = 0; d < 17; ++d) {
        float w = __shfl_sync(0xffffffffu, ead, d);
        acc = fmaf(w, __ldg(yrow + d * 32), acc);
    }
    float* hp = (which_h == 1 ? g_h1 : g_h2) + (size_t)dst * h_stride + o_base + lane;
    red1(hp, acc);
}

// ---------------- atom attention readout -> g_aa; also zeroes g_gg ----------------
__global__ void __launch_bounds__(128) k_attn(const int* __restrict__ labels,
                                              const float* __restrict__ wa_g,
                                              const float* __restrict__ ba_g) {
    extern __shared__ float sm[];
    float* sc = sm;
    float* wa = sm + 1000;
    float* red = sm + 1064;
    float* wacc = sm + 1192;

    int b = blockIdx.x, tid = threadIdx.x;
    const float* h2b = g_h2 + (size_t)b * NPG * H2D;
    if (tid < 64) wa[tid] = wa_g[tid];
    for (int i = tid; i < 4 * M_M * H2D; i += 128) wacc[i] = 0.0f;
    for (int i = tid; i < M_M * G_DIM; i += 128) g_gg[b * M_M * G_DIM + i] = 0.0f;
    __syncthreads();

    float ba = ba_g[0];
    for (int i = tid; i < NPG; i += 128) {
        const float4* r4 = (const float4*)(h2b + i * H2D);
        float s = ba;
#pragma unroll
        for (int o4 = 0; o4 < 16; ++o4) {
            float4 v = r4[o4];
            s = fmaf(fmaxf(v.x, 0.0f), wa[o4 * 4 + 0], s);
            s = fmaf(fmaxf(v.y, 0.0f), wa[o4 * 4 + 1], s);
            s = fmaf(fmaxf(v.z, 0.0f), wa[o4 * 4 + 2], s);
            s = fmaf(fmaxf(v.w, 0.0f), wa[o4 * 4 + 3], s);
        }
        sc[i] = s;
    }
    __syncthreads();
    float mx = -1e30f;
    for (int i = tid; i < NPG; i += 128) mx = fmaxf(mx, sc[i]);
    red[tid] = mx;
    __syncthreads();
    for (int s = 64; s > 0; s >>= 1) {
        if (tid < s) red[tid] = fmaxf(red[tid], red[tid + s]);
        __syncthreads();
    }
    mx = red[0];
    __syncthreads();
    float se = 0.0f;
    for (int i = tid; i < NPG; i += 128) {
        float e2 = expf(sc[i] - mx);
        sc[i] = e2;
        se += e2;
    }
    red[tid] = se;
    __syncthreads();
    for (int s = 64; s > 0; s >>= 1) {
        if (tid < s) red[tid] += red[tid + s];
        __syncthreads();
    }
    float inv = 1.0f / red[0];
    __syncthreads();

    int w = tid >> 5, lane = tid & 31;
    float* wp = wacc + w * (M_M * H2D);
    for (int i = w; i < NPG; i += 4) {
        int m = labels[b * NPG + i];
        float c = sc[i] * inv;
        const float* row = h2b + i * H2D;
        wp[m * H2D + lane]      += c * fmaxf(row[lane], 0.0f);
        wp[m * H2D + 32 + lane] += c * fmaxf(row[32 + lane], 0.0f);
    }
    __syncthreads();
    for (int i = tid; i < M_M * H2D; i += 128) {
        g_aa[b * M_M * H2D + i] =
            wacc[i] + wacc[3200 + i] + wacc[6400 + i] + wacc[9600 + i];
    }
}

// ---------------- ARMA (smem-staged weights, f32x2) ----------------
__device__ __forceinline__ void arma_mm2(u64 acc2[5][2], const float* __restrict__ xs,
                                         int xstride, int Fdim,
                                         const float* __restrict__ ws, int m0, int o0) {
    const float* x0p = xs + m0 * xstride;
    const float* x1p = x0p + xstride;
    const float* x2p = x1p + xstride;
    const float* x3p = x2p + xstride;
    const float* x4p = x3p + xstride;
    const float* wp = ws + o0;
#pragma unroll 4
    for (int f = 0; f < Fdim; ++f) {
        ulonglong2 wv = *(const ulonglong2*)(wp + f * G_DIM);
        u64 x0 = pk2(x0p[f], x0p[f]);
        fma2(acc2[0][0], x0, wv.x); fma2(acc2[0][1], x0, wv.y);
        u64 x1 = pk2(x1p[f], x1p[f]);
        fma2(acc2[1][0], x1, wv.x); fma2(acc2[1][1], x1, wv.y);
        u64 x2 = pk2(x2p[f], x2p[f]);
        fma2(acc2[2][0], x2, wv.x); fma2(acc2[2][1], x2, wv.y);
        u64 x3 = pk2(x3p[f], x3p[f]);
        fma2(acc2[3][0], x3, wv.x); fma2(acc2[3][1], x3, wv.y);
        u64 x4 = pk2(x4p[f], x4p[f]);
        fma2(acc2[4][0], x4, wv.x); fma2(acc2[4][1], x4, wv.y);
    }
}

__device__ __forceinline__ void stage_w(float* dstS, const float* __restrict__ src,
                                        int n4, int tid) {
    const float4* s4 = (const float4*)src;
    float4* d4 = (float4*)dstS;
    for (int i = tid; i < n4; i += 320) d4[i] = s4[i];
}

// smem floats: x0s[8000] | bufA[6400] | bufB[6400] | ws[20352] (at 20800)
__global__ void __launch_bounds__(320) k_arma(const float* __restrict__ aaf,
                                              const float* __restrict__ w_init,
                                              const float* __restrict__ w_mid,
                                              const float* __restrict__ w_root,
                                              const float* __restrict__ w_bias) {
    extern __shared__ float sm[];
    float* x0s = sm;
    float* bufA = sm + 8000;
    float* bufB = sm + 14400;
    float* ws = sm + 20800;

    int b = blockIdx.x / K_S, k = blockIdx.x % K_S;
    int tid = threadIdx.x;
    for (int i = tid; i < M_M * X0DIM; i += 320) {
        int m = i / X0DIM, f = i % X0DIM;
        float v = (f < H2D) ? g_aa[(b * M_M + m) * H2D + f]
                            : aaf[(b * M_M + m) * AAF + (f - H2D)];
        x0s[m * 160 + f] = v;
    }
    stage_w(ws, w_init + (size_t)k * X0DIM * G_DIM, X0DIM * G_DIM / 4, tid);
    __syncthreads();

    int warp = tid >> 5, lane = tid & 31;
    int m0 = warp * 5, o0 = lane * 4;
    u64 acc2[5][2];

#pragma unroll
    for (int mi = 0; mi < 5; ++mi) { acc2[mi][0] = 0ull; acc2[mi][1] = 0ull; }
    arma_mm2(acc2, x0s, 160, X0DIM, ws, m0, o0);
#pragma unroll
    for (int mi = 0; mi < 5; ++mi) {
        ulonglong2 v; v.x = acc2[mi][0]; v.y = acc2[mi][1];
        *(ulonglong2*)(bufA + (m0 + mi) * G_DIM + o0) = v;
    }
    __syncthreads();

    float accf[5][4];
    for (int t = 0; t < T_L; ++t) {
        const float* cur = bufA;
        if (t > 0) {
            stage_w(ws, w_mid + (size_t)((t - 1) * K_S + k) * G_DIM * G_DIM,
                    G_DIM * G_DIM / 4, tid);
            __syncthreads();
#pragma unroll
            for (int mi = 0; mi < 5; ++mi) { acc2[mi][0] = 0ull; acc2[mi][1] = 0ull; }
            arma_mm2(acc2, bufA, G_DIM, G_DIM, ws, m0, o0);
#pragma unroll
            for (int mi = 0; mi < 5; ++mi) {
                ulonglong2 v; v.x = acc2[mi][0]; v.y = acc2[mi][1];
                *(ulonglong2*)(bufB + (m0 + mi) * G_DIM + o0) = v;
            }
            __syncthreads();
            cur = bufB;
        }
        stage_w(ws, w_root + (size_t)(t * K_S + k) * X0DIM * G_DIM,
                X0DIM * G_DIM / 4, tid);
        __syncthreads();
#pragma unroll
        for (int mi = 0; mi < 5; ++mi) { acc2[mi][0] = 0ull; acc2[mi][1] = 0ull; }
        arma_mm2(acc2, x0s, 160, X0DIM, ws, m0, o0);
#pragma unroll
        for (int mi = 0; mi < 5; ++mi) {
            int m = m0 + mi;
            int e0 = g_aoff[m], e1 = g_aoff[m + 1];
            for (int e = e0; e < e1; ++e) {
                int s = g_asrc[e];
                u64 nr2 = pk2(g_anorm[e], g_anorm[e]);
                ulonglong2 cv = *(const ulonglong2*)(cur + s * G_DIM + o0);
                fma2(acc2[mi][0], nr2, cv.x);
                fma2(acc2[mi][1], nr2, cv.y);
            }
        }
        ulonglong2 bv = *(const ulonglong2*)(w_bias + (t * K_S + k) * G_DIM + o0);
#pragma unroll
        for (int mi = 0; mi < 5; ++mi) {
            add2(acc2[mi][0], bv.x);
            add2(acc2[mi][1], bv.y);
            float2 lo = up2(acc2[mi][0]), hi = up2(acc2[mi][1]);
            accf[mi][0] = fmaxf(lo.x, 0.0f); accf[mi][1] = fmaxf(lo.y, 0.0f);
            accf[mi][2] = fmaxf(hi.x, 0.0f); accf[mi][3] = fmaxf(hi.y, 0.0f);
        }
        __syncthreads();
#pragma unroll
        for (int mi = 0; mi < 5; ++mi)
            *(float4*)(bufA + (m0 + mi) * G_DIM + o0) =
                make_float4(accf[mi][0], accf[mi][1], accf[mi][2], accf[mi][3]);
        __syncthreads();
    }
    const float invK = 1.0f / (float)K_S;
#pragma unroll
    for (int mi = 0; mi < 5; ++mi)
        red4(&g_gg[b * M_M * G_DIM + (m0 + mi) * G_DIM + o0],
             accf[mi][0] * invK, accf[mi][1] * invK,
             accf[mi][2] * invK, accf[mi][3] * invK);
}

// ---------------- amino attention + MLP head ----------------
__global__ void __launch_bounds__(128) k_final(const float* __restrict__ waa,
                                               const float* __restrict__ baa,
                                               const float* __restrict__ W1,
                                               const float* __restrict__ b1,
                                               const float* __restrict__ W2,
                                               const float* __restrict__ b2,
                                               const float* __restrict__ W3,
                                               const float* __restrict__ b3,
                                               const float* __restrict__ W4,
                                               const float* __restrict__ b4,
                                               float* __restrict__ out) {
    __shared__ float gs[M_M * G_DIM];
    __shared__ float sc[M_M];
    __shared__ float p[G_DIM];
    __shared__ float f1[F1D];
    __shared__ float f2[F2D];
    __shared__ float f3[F3D];
    int b = blockIdx.x, tid = threadIdx.x;
    for (int i = tid; i < M_M * G_DIM; i += 128) gs[i] = g_gg[b * M_M * G_DIM + i];
    __syncthreads();
    if (tid < M_M) {
        float s = baa[0];
#pragma unroll 4
        for (int o = 0; o < G_DIM; ++o) s = fmaf(gs[tid * G_DIM + o], waa[o], s);
        sc[tid] = s;
    }
    __syncthreads();
    if (tid == 0) {
        float mx = -1e30f;
        for (int m = 0; m < M_M; ++m) mx = fmaxf(mx, sc[m]);
        float se = 0.0f;
        for (int m = 0; m < M_M; ++m) {
            float e = expf(sc[m] - mx);
            sc[m] = e;
            se += e;
        }
        float inv = 1.0f / se;
        for (int m = 0; m < M_M; ++m) sc[m] *= inv;
    }
    __syncthreads();
    {
        float pv = 0.0f;
        for (int m = 0; m < M_M; ++m) pv = fmaf(sc[m], gs[m * G_DIM + tid], pv);
        p[tid] = pv;
    }
    __syncthreads();
    if (tid < F1D) {
        float v = b1[tid];
        for (int i = 0; i < G_DIM; ++i) v = fmaf(p[i], W1[i * F1D + tid], v);
        f1[tid] = fmaxf(v, 0.0f);
    }
    __syncthreads();
    if (tid < F2D) {
        float v = b2[tid];
        for (int i = 0; i < F1D; ++i) v = fmaf(f1[i], W2[i * F2D + tid], v);
        f2[tid] = fmaxf(v, 0.0f);
    }
    __syncthreads();
    if (tid < F3D) {
        float v = b3[tid];
        for (int i = 0; i < F2D; ++i) v = fmaf(f2[i], W3[i * F3D + tid], v);
        f3[tid] = fmaxf(v, 0.0f);
    }
    __syncthreads();
    if (tid == 0) {
        float v = b4[0];
        for (int i = 0; i < F3D; ++i) v = fmaf(f3[i], W4[i], v);
        out[b] = v;
    }
}

// ---------------- launch ----------------
extern "C" void kernel_launch(void* const* d_in, const int* in_sizes, int n_in,
                              void* d_out, int out_size) {
    const float* x              = (const float*)d_in[0];
    const float* edge_attr      = (const float*)d_in[1];
    const float* aa_features    = (const float*)d_in[2];
    const int*   edge_index     = (const int*)d_in[3];
    const int*   monomer_labels = (const int*)d_in[4];
    const int*   amino_edge_idx = (const int*)d_in[5];
    const float* W_e1   = (const float*)d_in[6];
    const float* b_e1   = (const float*)d_in[7];
    const float* root1  = (const float*)d_in[8];
    const float* bias1  = (const float*)d_in[9];
    const float* W_e2   = (const float*)d_in[10];
    const float* b_e2   = (const float*)d_in[11];
    const float* root2  = (const float*)d_in[12];
    const float* bias2  = (const float*)d_in[13];
    const float* Wa_atom = (const float*)d_in[14];
    const float* ba_atom = (const float*)d_in[15];
    const float* arma_init_w = (const float*)d_in[16];
    const float* arma_w      = (const float*)d_in[17];
    const float* arma_root_w = (const float*)d_in[18];
    const float* arma_bias   = (const float*)d_in[19];
    const float* Wa_aa = (const float*)d_in[20];
    const float* ba_aa = (const float*)d_in[21];
    const float* W1 = (const float*)d_in[22];
    const float* b1 = (const float*)d_in[23];
    const float* W2 = (const float*)d_in[24];
    const float* b2 = (const float*)d_in[25];
    const float* W3 = (const float*)d_in[26];
    const float* b3 = (const float*)d_in[27];
    const float* W4 = (const float*)d_in[28];
    const float* b4 = (const float*)d_in[29];
    float* out = (float*)d_out;

    const int YG_SMEM   = (8192 + 2048 + 32) * 4;            // 41088 B
    const int ATTN_SMEM = (1000 + 64 + 128 + 12800) * 4;     // 55968 B
    const int ARMA_SMEM = (20800 + 20352) * 4;               // 164608 B
    cudaFuncSetAttribute(k_ygemm, cudaFuncAttributeMaxDynamicSharedMemorySize, YG_SMEM);
    cudaFuncSetAttribute(k_attn, cudaFuncAttributeMaxDynamicSharedMemorySize, ATTN_SMEM);
    cudaFuncSetAttribute(k_arma, cudaFuncAttributeMaxDynamicSharedMemorySize, ARMA_SMEM);

    dim3 YG_GRID((N_ATOMS + 255) / 256, 9);      // 196 x 9
    const int ECON_GRID = N_EDGES / 8;           // 12500

    k_amino_prep<<<1, 32>>>(amino_edge_idx);

    // conv1
    k_ygemm<<<YG_GRID, 256, YG_SMEM>>>(x, 0, 0, W_e1, b_e1, root1, bias1, 32, 0, 1, H1D);
    k_econ<<<ECON_GRID, 256>>>(edge_index, edge_attr, 1, H1D, 0);

    // conv2 half 0 (outputs 0..31)
    k_ygemm<<<YG_GRID, 256, YG_SMEM>>>(x, 1, 1, W_e2, b_e2, root2, bias2, 64, 0, 2, H2D);
    k_econ<<<ECON_GRID, 256>>>(edge_index, edge_attr, 2, H2D, 0);

    // conv2 half 1 (outputs 32..63)
    k_ygemm<<<YG_GRID, 256, YG_SMEM>>>(x, 1, 1, W_e2, b_e2, root2, bias2, 64, 32, 2, H2D);
    k_econ<<<ECON_GRID, 256>>>(edge_index, edge_attr, 2, H2D, 32);

    k_attn<<<B_G, 128, ATTN_SMEM>>>(monomer_labels, Wa_atom, ba_atom);
    k_arma<<<B_G * K_S, 320, ARMA_SMEM>>>(aa_features, arma_init_w, arma_w, arma_root_w, arma_bias);
    k_final<<<B_G, 128>>>(Wa_aa, ba_aa, W1, b1, W2, b2, W3, b3, W4, b4, out);
}

// round 5
// speedup vs baseline: 1.5862x; 1.0374x over previous
#include <cuda_runtime.h>
#include <math.h>

#define N_ATOMS 50000
#define N_EDGES 100000
#define B_G 50
#define M_M 50
#define NPG 1000
#define DIN 32
#define H1D 32
#define H2D 64
#define DE 16
#define AAF 95
#define G_DIM 128
#define K_S 3
#define T_L 6
#define EA 98
#define F1D 64
#define F2D 32
#define F3D 16
#define X0DIM 159
#define X0PAD 160
#define YSTRIDE 576   /* 18 * 32 */

typedef unsigned long long u64;

// ---------------- f32x2 helpers ----------------
__device__ __forceinline__ u64 pk2(float a, float b) {
    u64 r;
    asm("mov.b64 %0, {%1, %2};" : "=l"(r) : "f"(a), "f"(b));
    return r;
}
__device__ __forceinline__ void fma2(u64& d, u64 a, u64 b) {
    asm("fma.rn.f32x2 %0, %1, %2, %3;" : "=l"(d) : "l"(a), "l"(b), "l"(d));
}
__device__ __forceinline__ void add2(u64& d, u64 a) {
    asm("add.rn.f32x2 %0, %1, %2;" : "=l"(d) : "l"(a), "l"(d));
}
__device__ __forceinline__ float2 up2(u64 v) {
    float2 f;
    asm("mov.b64 {%0, %1}, %2;" : "=f"(f.x), "=f"(f.y) : "l"(v));
    return f;
}
__device__ __forceinline__ void red1(float* p, float a) {
    asm volatile("red.global.add.f32 [%0], %1;" :: "l"(p), "f"(a) : "memory");
}
__device__ __forceinline__ void red4(float* p, float a, float b, float c, float d) {
    asm volatile("red.global.add.v4.f32 [%0], {%1, %2, %3, %4};"
                 :: "l"(p), "f"(a), "f"(b), "f"(c), "f"(d) : "memory");
}

// ---------------- scratch ----------------
__device__ float g_y[(size_t)N_ATOMS * YSTRIDE];
__device__ float g_h1[N_ATOMS * H1D];
__device__ float g_h2[N_ATOMS * H2D];
__device__ float g_aa[B_G * M_M * H2D];
__device__ float g_gg[B_G * M_M * G_DIM];
__device__ int   g_aoff[M_M + 1];
__device__ int   g_asrc[EA];
__device__ float g_anorm[EA];

// ---------------- amino graph prep ----------------
__global__ void k_amino_prep(const int* __restrict__ aei) {
    if (threadIdx.x != 0 || blockIdx.x != 0) return;
    int deg[M_M]; float dinv[M_M]; int off[M_M + 1]; int cnt[M_M];
    for (int m = 0; m < M_M; ++m) { deg[m] = 0; cnt[m] = 0; }
    for (int e = 0; e < EA; ++e) deg[aei[EA + e]]++;
    for (int m = 0; m < M_M; ++m)
        dinv[m] = (deg[m] > 0) ? (1.0f / sqrtf((float)deg[m])) : 0.0f;
    off[0] = 0;
    for (int m = 0; m < M_M; ++m) off[m + 1] = off[m] + deg[m];
    for (int e = 0; e < EA; ++e) {
        int s = aei[e], d = aei[EA + e];
        int slot = off[d] + cnt[d]++;
        g_asrc[slot] = s;
        g_anorm[slot] = dinv[s] * dinv[d];
    }
    for (int m = 0; m <= M_M; ++m) g_aoff[m] = off[m];
}

// ---------------- node GEMM v3: y[n, 576] = h[n,:] @ Waug ----------------
// Block: 256 nodes, 3 col-tiles of 64. Thread: 8 nodes x 8 cols.
// smem: sh[32][256] (h transposed), sw2[32][128] (weights duplicated as (w,w) pairs,
//       chunk-interleaved: float idx = f*128 + j*32 + tx*4 + odd*2), sb[32]
__global__ void __launch_bounds__(256, 2) k_ygemm(const float* __restrict__ xin,
                                                  int hin_sel, int relu,
                                                  const float* __restrict__ We,
                                                  const float* __restrict__ be,
                                                  const float* __restrict__ root,
                                                  const float* __restrict__ bias,
                                                  int o_total, int o_base,
                                                  int which_h, int h_stride) {
    extern __shared__ float sm_[];
    float* sh = sm_;                  // 8192 floats
    float* sw2 = sm_ + 8192;          // 4096 floats
    float* sb = sm_ + 8192 + 4096;    // 32 floats

    int tid = threadIdx.x;
    int n0 = blockIdx.x * 256;
    const float* hin = hin_sel ? g_h1 : xin;
    int lane = tid & 31, wrp = tid >> 5;

    // stage h transposed [f][n]
#pragma unroll
    for (int it = 0; it < 8; ++it) {
        int n = it * 32 + lane;
        int gn = n0 + n;
        float4 v = make_float4(0.f, 0.f, 0.f, 0.f);
        if (gn < N_ATOMS) v = *(const float4*)(hin + (size_t)gn * 32 + wrp * 4);
        if (relu) {
            v.x = fmaxf(v.x, 0.f); v.y = fmaxf(v.y, 0.f);
            v.z = fmaxf(v.z, 0.f); v.w = fmaxf(v.w, 0.f);
        }
        sh[(wrp * 4 + 0) * 256 + n] = v.x;
        sh[(wrp * 4 + 1) * 256 + n] = v.y;
        sh[(wrp * 4 + 2) * 256 + n] = v.z;
        sh[(wrp * 4 + 3) * 256 + n] = v.w;
    }
    if (tid < 32) sb[tid] = bias[o_base + tid];

    int tx = tid & 7;     // 8 cols
    int ty = tid >> 3;    // 8-node group

    for (int ct3 = 0; ct3 < 3; ++ct3) {
        int ct = blockIdx.y * 3 + ct3;
        __syncthreads();  // prior tile reads (and initial h staging) complete
        // stage duplicated weights for this 64-col tile
        for (int i = tid; i < 2048; i += 256) {
            int f = i >> 6, cc = i & 63;
            int c = ct * 64 + cc;
            int d = c >> 5, o = c & 31;
            float v;
            if (d < 16)       v = We[(d * 32 + f) * o_total + o_base + o];
            else if (d == 16) v = be[f * o_total + o_base + o];
            else              v = root[f * o_total + o_base + o];
            int txx = cc >> 3, w8 = cc & 7, j = w8 >> 1, odd = w8 & 1;
            int bi = f * 128 + j * 32 + txx * 4 + odd * 2;
            sw2[bi] = v;
            sw2[bi + 1] = v;
        }
        __syncthreads();

        u64 acc[4][8];
#pragma unroll
        for (int p = 0; p < 4; ++p)
#pragma unroll
            for (int c = 0; c < 8; ++c) acc[p][c] = 0ull;

#pragma unroll 8
        for (int f = 0; f < 32; ++f) {
            const float* fb = sh + f * 256 + ty * 8;
            ulonglong2 hA = *(const ulonglong2*)(fb);       // pairs (n0,n1),(n2,n3)
            ulonglong2 hB = *(const ulonglong2*)(fb + 4);   // pairs (n4,n5),(n6,n7)
            const float* wb = sw2 + f * 128 + tx * 4;
            ulonglong2 w0 = *(const ulonglong2*)(wb);        // (c0c0),(c1c1)
            ulonglong2 w1 = *(const ulonglong2*)(wb + 32);   // c2,c3
            ulonglong2 w2 = *(const ulonglong2*)(wb + 64);   // c4,c5
            ulonglong2 w3 = *(const ulonglong2*)(wb + 96);   // c6,c7
            u64 hh[4] = {hA.x, hA.y, hB.x, hB.y};
            u64 ww[8] = {w0.x, w0.y, w1.x, w1.y, w2.x, w2.y, w3.x, w3.y};
#pragma unroll
            for (int p = 0; p < 4; ++p)
#pragma unroll
                for (int c = 0; c < 8; ++c)
                    fma2(acc[p][c], hh[p], ww[c]);
        }

        int c0 = ct * 64 + tx * 8;
        int d = c0 >> 5, o0 = c0 & 31;
        int nb = n0 + ty * 8;
        if (d < 17) {
#pragma unroll
            for (int r = 0; r < 8; ++r) {
                int n = nb + r;
                if (n < N_ATOMS) {
                    int p = r >> 1;
                    float v[8];
#pragma unroll
                    for (int c = 0; c < 8; ++c) {
                        float2 t = up2(acc[p][c]);
                        v[c] = (r & 1) ? t.y : t.x;
                    }
                    float* yp = g_y + (size_t)n * YSTRIDE + d * 32 + o0;
                    *(float4*)(yp)     = make_float4(v[0], v[1], v[2], v[3]);
                    *(float4*)(yp + 4) = make_float4(v[4], v[5], v[6], v[7]);
                }
            }
        } else {
            float* hbase = (which_h == 1 ? g_h1 : g_h2);
#pragma unroll
            for (int r = 0; r < 8; ++r) {
                int n = nb + r;
                if (n < N_ATOMS) {
                    int p = r >> 1;
                    float v[8];
#pragma unroll
                    for (int c = 0; c < 8; ++c) {
                        float2 t = up2(acc[p][c]);
                        v[c] = ((r & 1) ? t.y : t.x) + sb[o0 + c];
                    }
                    float* hp = hbase + (size_t)n * h_stride + o_base + o0;
                    *(float4*)(hp)     = make_float4(v[0], v[1], v[2], v[3]);
                    *(float4*)(hp + 4) = make_float4(v[4], v[5], v[6], v[7]);
                }
            }
        }
    }
}

// ---------------- edge contraction ----------------
__global__ void __launch_bounds__(256) k_econ(const int* __restrict__ eidx,
                                              const float* __restrict__ ea_g,
                                              int which_h, int h_stride, int o_base) {
    int warp = threadIdx.x >> 5, lane = threadIdx.x & 31;
    int e = blockIdx.x * 8 + warp;
    int src = __ldg(eidx + e);
    int dst = __ldg(eidx + N_EDGES + e);
    float ead = (lane < 16) ? __ldg(ea_g + e * 16 + lane) : 1.0f;
    const float* yrow = g_y + (size_t)src * YSTRIDE + lane;
    float acc = 0.0f;
#pragma unroll
    for (int d = 0; d < 17; ++d) {
        float w = __shfl_sync(0xffffffffu, ead, d);
        acc = fmaf(w, __ldg(yrow + d * 32), acc);
    }
    float* hp = (which_h == 1 ? g_h1 : g_h2) + (size_t)dst * h_stride + o_base + lane;
    red1(hp, acc);
}

// ---------------- atom attention readout ----------------
__global__ void __launch_bounds__(128) k_attn(const int* __restrict__ labels,
                                              const float* __restrict__ wa_g,
                                              const float* __restrict__ ba_g) {
    extern __shared__ float sm[];
    float* sc = sm;
    float* wa = sm + 1000;
    float* red = sm + 1064;
    float* wacc = sm + 1192;

    int b = blockIdx.x, tid = threadIdx.x;
    const float* h2b = g_h2 + (size_t)b * NPG * H2D;
    if (tid < 64) wa[tid] = wa_g[tid];
    for (int i = tid; i < 4 * M_M * H2D; i += 128) wacc[i] = 0.0f;
    for (int i = tid; i < M_M * G_DIM; i += 128) g_gg[b * M_M * G_DIM + i] = 0.0f;
    __syncthreads();

    float ba = ba_g[0];
    for (int i = tid; i < NPG; i += 128) {
        const float4* r4 = (const float4*)(h2b + i * H2D);
        float s = ba;
#pragma unroll
        for (int o4 = 0; o4 < 16; ++o4) {
            float4 v = r4[o4];
            s = fmaf(fmaxf(v.x, 0.0f), wa[o4 * 4 + 0], s);
            s = fmaf(fmaxf(v.y, 0.0f), wa[o4 * 4 + 1], s);
            s = fmaf(fmaxf(v.z, 0.0f), wa[o4 * 4 + 2], s);
            s = fmaf(fmaxf(v.w, 0.0f), wa[o4 * 4 + 3], s);
        }
        sc[i] = s;
    }
    __syncthreads();
    float mx = -1e30f;
    for (int i = tid; i < NPG; i += 128) mx = fmaxf(mx, sc[i]);
    red[tid] = mx;
    __syncthreads();
    for (int s = 64; s > 0; s >>= 1) {
        if (tid < s) red[tid] = fmaxf(red[tid], red[tid + s]);
        __syncthreads();
    }
    mx = red[0];
    __syncthreads();
    float se = 0.0f;
    for (int i = tid; i < NPG; i += 128) {
        float e2 = expf(sc[i] - mx);
        sc[i] = e2;
        se += e2;
    }
    red[tid] = se;
    __syncthreads();
    for (int s = 64; s > 0; s >>= 1) {
        if (tid < s) red[tid] += red[tid + s];
        __syncthreads();
    }
    float inv = 1.0f / red[0];
    __syncthreads();

    int w = tid >> 5, lane = tid & 31;
    float* wp = wacc + w * (M_M * H2D);
    for (int i = w; i < NPG; i += 4) {
        int m = labels[b * NPG + i];
        float c = sc[i] * inv;
        const float* row = h2b + i * H2D;
        wp[m * H2D + lane]      += c * fmaxf(row[lane], 0.0f);
        wp[m * H2D + 32 + lane] += c * fmaxf(row[32 + lane], 0.0f);
    }
    __syncthreads();
    for (int i = tid; i < M_M * H2D; i += 128) {
        g_aa[b * M_M * H2D + i] =
            wacc[i] + wacc[3200 + i] + wacc[6400 + i] + wacc[9600 + i];
    }
}

// ---------------- ARMA (float4 x loads, f32x2) ----------------
// F must be a multiple of 4.
__device__ __forceinline__ void arma_mm2(u64 acc2[5][2], const float* __restrict__ xs,
                                         int xstride, int F,
                                         const float* __restrict__ ws, int m0, int o0) {
    const float* x0p = xs + m0 * xstride;
    const float* x1p = x0p + xstride;
    const float* x2p = x1p + xstride;
    const float* x3p = x2p + xstride;
    const float* x4p = x3p + xstride;
    const float* wp = ws + o0;
#pragma unroll 2
    for (int f = 0; f < F; f += 4) {
        float4 a0 = *(const float4*)(x0p + f);
        float4 a1 = *(const float4*)(x1p + f);
        float4 a2 = *(const float4*)(x2p + f);
        float4 a3 = *(const float4*)(x3p + f);
        float4 a4 = *(const float4*)(x4p + f);
        float xa[5][4] = {
            {a0.x, a0.y, a0.z, a0.w},
            {a1.x, a1.y, a1.z, a1.w},
            {a2.x, a2.y, a2.z, a2.w},
            {a3.x, a3.y, a3.z, a3.w},
            {a4.x, a4.y, a4.z, a4.w}};
#pragma unroll
        for (int j = 0; j < 4; ++j) {
            ulonglong2 wv = *(const ulonglong2*)(wp + (f + j) * G_DIM);
#pragma unroll
            for (int r = 0; r < 5; ++r) {
                u64 xv = pk2(xa[r][j], xa[r][j]);
                fma2(acc2[r][0], xv, wv.x);
                fma2(acc2[r][1], xv, wv.y);
            }
        }
    }
}

__device__ __forceinline__ void stage_w(float* dstS, const float* __restrict__ src,
                                        int n4, int tid) {
    const float4* s4 = (const float4*)src;
    float4* d4 = (float4*)dstS;
    for (int i = tid; i < n4; i += 320) d4[i] = s4[i];
}

// smem floats: x0s[50*160=8000] | bufA[6400] | bufB[6400] | ws[160*128=20480] (at 20800)
__global__ void __launch_bounds__(320) k_arma(const float* __restrict__ aaf,
                                              const float* __restrict__ w_init,
                                              const float* __restrict__ w_mid,
                                              const float* __restrict__ w_root,
                                              const float* __restrict__ w_bias) {
    extern __shared__ float sm[];
    float* x0s = sm;
    float* bufA = sm + 8000;
    float* bufB = sm + 14400;
    float* ws = sm + 20800;

    int b = blockIdx.x / K_S, k = blockIdx.x % K_S;
    int tid = threadIdx.x;
    for (int i = tid; i < M_M * X0PAD; i += 320) {
        int m = i / X0PAD, f = i % X0PAD;
        float v = 0.0f;
        if (f < H2D)        v = g_aa[(b * M_M + m) * H2D + f];
        else if (f < X0DIM) v = aaf[(b * M_M + m) * AAF + (f - H2D)];
        x0s[m * X0PAD + f] = v;
    }
    // zero pad row f=159 of ws once (later stages never touch it for F=160 GEMMs beyond row 158)
    for (int i = tid; i < G_DIM; i += 320) ws[X0DIM * G_DIM + i] = 0.0f;
    stage_w(ws, w_init + (size_t)k * X0DIM * G_DIM, X0DIM * G_DIM / 4, tid);
    __syncthreads();

    int warp = tid >> 5, lane = tid & 31;
    int m0 = warp * 5, o0 = lane * 4;
    u64 acc2[5][2];

#pragma unroll
    for (int mi = 0; mi < 5; ++mi) { acc2[mi][0] = 0ull; acc2[mi][1] = 0ull; }
    arma_mm2(acc2, x0s, X0PAD, X0PAD, ws, m0, o0);
#pragma unroll
    for (int mi = 0; mi < 5; ++mi) {
        ulonglong2 v; v.x = acc2[mi][0]; v.y = acc2[mi][1];
        *(ulonglong2*)(bufA + (m0 + mi) * G_DIM + o0) = v;
    }
    __syncthreads();

    float accf[5][4];
    for (int t = 0; t < T_L; ++t) {
        const float* cur = bufA;
        if (t > 0) {
            stage_w(ws, w_mid + (size_t)((t - 1) * K_S + k) * G_DIM * G_DIM,
                    G_DIM * G_DIM / 4, tid);
            __syncthreads();
#pragma unroll
            for (int mi = 0; mi < 5; ++mi) { acc2[mi][0] = 0ull; acc2[mi][1] = 0ull; }
            arma_mm2(acc2, bufA, G_DIM, G_DIM, ws, m0, o0);
#pragma unroll
            for (int mi = 0; mi < 5; ++mi) {
                ulonglong2 v; v.x = acc2[mi][0]; v.y = acc2[mi][1];
                *(ulonglong2*)(bufB + (m0 + mi) * G_DIM + o0) = v;
            }
            __syncthreads();
            cur = bufB;
        }
        stage_w(ws, w_root + (size_t)(t * K_S + k) * X0DIM * G_DIM,
                X0DIM * G_DIM / 4, tid);
        __syncthreads();
#pragma unroll
        for (int mi = 0; mi < 5; ++mi) { acc2[mi][0] = 0ull; acc2[mi][1] = 0ull; }
        arma_mm2(acc2, x0s, X0PAD, X0PAD, ws, m0, o0);
#pragma unroll
        for (int mi = 0; mi < 5; ++mi) {
            int m = m0 + mi;
            int e0 = g_aoff[m], e1 = g_aoff[m + 1];
            for (int e = e0; e < e1; ++e) {
                int s = g_asrc[e];
                u64 nr2 = pk2(g_anorm[e], g_anorm[e]);
                ulonglong2 cv = *(const ulonglong2*)(cur + s * G_DIM + o0);
                fma2(acc2[mi][0], nr2, cv.x);
                fma2(acc2[mi][1], nr2, cv.y);
            }
        }
        ulonglong2 bv = *(const ulonglong2*)(w_bias + (t * K_S + k) * G_DIM + o0);
#pragma unroll
        for (int mi = 0; mi < 5; ++mi) {
            add2(acc2[mi][0], bv.x);
            add2(acc2[mi][1], bv.y);
            float2 lo = up2(acc2[mi][0]), hi = up2(acc2[mi][1]);
            accf[mi][0] = fmaxf(lo.x, 0.0f); accf[mi][1] = fmaxf(lo.y, 0.0f);
            accf[mi][2] = fmaxf(hi.x, 0.0f); accf[mi][3] = fmaxf(hi.y, 0.0f);
        }
        __syncthreads();
#pragma unroll
        for (int mi = 0; mi < 5; ++mi)
            *(float4*)(bufA + (m0 + mi) * G_DIM + o0) =
                make_float4(accf[mi][0], accf[mi][1], accf[mi][2], accf[mi][3]);
        __syncthreads();
    }
    const float invK = 1.0f / (float)K_S;
#pragma unroll
    for (int mi = 0; mi < 5; ++mi)
        red4(&g_gg[b * M_M * G_DIM + (m0 + mi) * G_DIM + o0],
             accf[mi][0] * invK, accf[mi][1] * invK,
             accf[mi][2] * invK, accf[mi][3] * invK);
}

// ---------------- amino attention + MLP head ----------------
__global__ void __launch_bounds__(128) k_final(const float* __restrict__ waa,
                                               const float* __restrict__ baa,
                                               const float* __restrict__ W1,
                                               const float* __restrict__ b1,
                                               const float* __restrict__ W2,
                                               const float* __restrict__ b2,
                                               const float* __restrict__ W3,
                                               const float* __restrict__ b3,
                                               const float* __restrict__ W4,
                                               const float* __restrict__ b4,
                                               float* __restrict__ out) {
    __shared__ float gs[M_M * G_DIM];
    __shared__ float sc[M_M];
    __shared__ float p[G_DIM];
    __shared__ float f1[F1D];
    __shared__ float f2[F2D];
    __shared__ float f3[F3D];
    int b = blockIdx.x, tid = threadIdx.x;
    for (int i = tid; i < M_M * G_DIM; i += 128) gs[i] = g_gg[b * M_M * G_DIM + i];
    __syncthreads();
    if (tid < M_M) {
        float s = baa[0];
#pragma unroll 4
        for (int o = 0; o < G_DIM; ++o) s = fmaf(gs[tid * G_DIM + o], waa[o], s);
        sc[tid] = s;
    }
    __syncthreads();
    if (tid == 0) {
        float mx = -1e30f;
        for (int m = 0; m < M_M; ++m) mx = fmaxf(mx, sc[m]);
        float se = 0.0f;
        for (int m = 0; m < M_M; ++m) {
            float e = expf(sc[m] - mx);
            sc[m] = e;
            se += e;
        }
        float inv = 1.0f / se;
        for (int m = 0; m < M_M; ++m) sc[m] *= inv;
    }
    __syncthreads();
    {
        float pv = 0.0f;
        for (int m = 0; m < M_M; ++m) pv = fmaf(sc[m], gs[m * G_DIM + tid], pv);
        p[tid] = pv;
    }
    __syncthreads();
    if (tid < F1D) {
        float v = b1[tid];
        for (int i = 0; i < G_DIM; ++i) v = fmaf(p[i], W1[i * F1D + tid], v);
        f1[tid] = fmaxf(v, 0.0f);
    }
    __syncthreads();
    if (tid < F2D) {
        float v = b2[tid];
        for (int i = 0; i < F1D; ++i) v = fmaf(f1[i], W2[i * F2D + tid], v);
        f2[tid] = fmaxf(v, 0.0f);
    }
    __syncthreads();
    if (tid < F3D) {
        float v = b3[tid];
        for (int i = 0; i < F2D; ++i) v = fmaf(f2[i], W3[i * F3D + tid], v);
        f3[tid] = fmaxf(v, 0.0f);
    }
    __syncthreads();
    if (tid == 0) {
        float v = b4[0];
        for (int i = 0; i < F3D; ++i) v = fmaf(f3[i], W4[i], v);
        out[b] = v;
    }
}

// ---------------- launch ----------------
extern "C" void kernel_launch(void* const* d_in, const int* in_sizes, int n_in,
                              void* d_out, int out_size) {
    const float* x              = (const float*)d_in[0];
    const float* edge_attr      = (const float*)d_in[1];
    const float* aa_features    = (const float*)d_in[2];
    const int*   edge_index     = (const int*)d_in[3];
    const int*   monomer_labels = (const int*)d_in[4];
    const int*   amino_edge_idx = (const int*)d_in[5];
    const float* W_e1   = (const float*)d_in[6];
    const float* b_e1   = (const float*)d_in[7];
    const float* root1  = (const float*)d_in[8];
    const float* bias1  = (const float*)d_in[9];
    const float* W_e2   = (const float*)d_in[10];
    const float* b_e2   = (const float*)d_in[11];
    const float* root2  = (const float*)d_in[12];
    const float* bias2  = (const float*)d_in[13];
    const float* Wa_atom = (const float*)d_in[14];
    const float* ba_atom = (const float*)d_in[15];
    const float* arma_init_w = (const float*)d_in[16];
    const float* arma_w      = (const float*)d_in[17];
    const float* arma_root_w = (const float*)d_in[18];
    const float* arma_bias   = (const float*)d_in[19];
    const float* Wa_aa = (const float*)d_in[20];
    const float* ba_aa = (const float*)d_in[21];
    const float* W1 = (const float*)d_in[22];
    const float* b1 = (const float*)d_in[23];
    const float* W2 = (const float*)d_in[24];
    const float* b2 = (const float*)d_in[25];
    const float* W3 = (const float*)d_in[26];
    const float* b3 = (const float*)d_in[27];
    const float* W4 = (const float*)d_in[28];
    const float* b4 = (const float*)d_in[29];
    float* out = (float*)d_out;

    const int YG_SMEM   = (8192 + 4096 + 32) * 4;            // 49280 B
    const int ATTN_SMEM = (1000 + 64 + 128 + 12800) * 4;     // 55968 B
    const int ARMA_SMEM = (20800 + 20480) * 4;               // 165120 B
    cudaFuncSetAttribute(k_ygemm, cudaFuncAttributeMaxDynamicSharedMemorySize, YG_SMEM);
    cudaFuncSetAttribute(k_attn, cudaFuncAttributeMaxDynamicSharedMemorySize, ATTN_SMEM);
    cudaFuncSetAttribute(k_arma, cudaFuncAttributeMaxDynamicSharedMemorySize, ARMA_SMEM);

    dim3 YG_GRID((N_ATOMS + 255) / 256, 3);      // 196 x 3 (3 col-tiles each)
    const int ECON_GRID = N_EDGES / 8;           // 12500

    k_amino_prep<<<1, 32>>>(amino_edge_idx);

    // conv1
    k_ygemm<<<YG_GRID, 256, YG_SMEM>>>(x, 0, 0, W_e1, b_e1, root1, bias1, 32, 0, 1, H1D);
    k_econ<<<ECON_GRID, 256>>>(edge_index, edge_attr, 1, H1D, 0);

    // conv2 half 0 (outputs 0..31)
    k_ygemm<<<YG_GRID, 256, YG_SMEM>>>(x, 1, 1, W_e2, b_e2, root2, bias2, 64, 0, 2, H2D);
    k_econ<<<ECON_GRID, 256>>>(edge_index, edge_attr, 2, H2D, 0);

    // conv2 half 1 (outputs 32..63)
    k_ygemm<<<YG_GRID, 256, YG_SMEM>>>(x, 1, 1, W_e2, b_e2, root2, bias2, 64, 32, 2, H2D);
    k_econ<<<ECON_GRID, 256>>>(edge_index, edge_attr, 2, H2D, 32);

    k_attn<<<B_G, 128, ATTN_SMEM>>>(monomer_labels, Wa_atom, ba_atom);
    k_arma<<<B_G * K_S, 320, ARMA_SMEM>>>(aa_features, arma_init_w, arma_w, arma_root_w, arma_bias);
    k_final<<<B_G, 128>>>(Wa_aa, ba_aa, W1, b1, W2, b2, W3, b3, W4, b4, out);
}

// round 6
// speedup vs baseline: 1.6447x; 1.0369x over previous
#include <cuda_runtime.h>
#include <math.h>

#define N_ATOMS 50000
#define N_EDGES 100000
#define B_G 50
#define M_M 50
#define NPG 1000
#define DIN 32
#define H1D 32
#define H2D 64
#define DE 16
#define AAF 95
#define G_DIM 128
#define K_S 3
#define T_L 6
#define EA 98
#define F1D 64
#define F2D 32
#define F3D 16
#define X0DIM 159
#define X0PAD 160
#define YSTRIDE 576   /* 18 * 32 */

typedef unsigned long long u64;

// ---------------- f32x2 helpers ----------------
__device__ __forceinline__ u64 pk2(float a, float b) {
    u64 r;
    asm("mov.b64 %0, {%1, %2};" : "=l"(r) : "f"(a), "f"(b));
    return r;
}
__device__ __forceinline__ void fma2(u64& d, u64 a, u64 b) {
    asm("fma.rn.f32x2 %0, %1, %2, %3;" : "=l"(d) : "l"(a), "l"(b), "l"(d));
}
__device__ __forceinline__ void add2(u64& d, u64 a) {
    asm("add.rn.f32x2 %0, %1, %2;" : "=l"(d) : "l"(a), "l"(d));
}
__device__ __forceinline__ float2 up2(u64 v) {
    float2 f;
    asm("mov.b64 {%0, %1}, %2;" : "=f"(f.x), "=f"(f.y) : "l"(v));
    return f;
}
__device__ __forceinline__ void red1(float* p, float a) {
    asm volatile("red.global.add.f32 [%0], %1;" :: "l"(p), "f"(a) : "memory");
}
__device__ __forceinline__ void red4(float* p, float a, float b, float c, float d) {
    asm volatile("red.global.add.v4.f32 [%0], {%1, %2, %3, %4};"
                 :: "l"(p), "f"(a), "f"(b), "f"(c), "f"(d) : "memory");
}

// ---------------- scratch ----------------
__device__ float g_y[(size_t)N_ATOMS * YSTRIDE];
__device__ float g_h1[N_ATOMS * H1D];
__device__ float g_h2[N_ATOMS * H2D];
__device__ float g_aa[B_G * M_M * H2D];
__device__ float g_gg[B_G * M_M * G_DIM];
__device__ int   g_aoff[M_M + 1];
__device__ int   g_asrc[EA];
__device__ float g_anorm[EA];

// ---------------- amino graph prep ----------------
__global__ void k_amino_prep(const int* __restrict__ aei) {
    if (threadIdx.x != 0 || blockIdx.x != 0) return;
    int deg[M_M]; float dinv[M_M]; int off[M_M + 1]; int cnt[M_M];
    for (int m = 0; m < M_M; ++m) { deg[m] = 0; cnt[m] = 0; }
    for (int e = 0; e < EA; ++e) deg[aei[EA + e]]++;
    for (int m = 0; m < M_M; ++m)
        dinv[m] = (deg[m] > 0) ? (1.0f / sqrtf((float)deg[m])) : 0.0f;
    off[0] = 0;
    for (int m = 0; m < M_M; ++m) off[m + 1] = off[m] + deg[m];
    for (int e = 0; e < EA; ++e) {
        int s = aei[e], d = aei[EA + e];
        int slot = off[d] + cnt[d]++;
        g_asrc[slot] = s;
        g_anorm[slot] = dinv[s] * dinv[d];
    }
    for (int m = 0; m <= M_M; ++m) g_aoff[m] = off[m];
}

// ---------------- node GEMM v4: y[n, 576] = h[n,:] @ Waug ----------------
// Block: 256 nodes, 3 col-tiles of 64. Thread: 8 nodes (4 pairs) x 8 cols.
// Natural layouts both sides; w duplicated IN REGISTERS (mov.b64 {w,w}) to
// keep smem crossbar traffic at 64B/thread/f (balanced vs FFMA2 pipe).
// smem: sh[32][256] (h transposed), sw[32][64], sb[32]
__global__ void __launch_bounds__(256, 2) k_ygemm(const float* __restrict__ xin,
                                                  int hin_sel, int relu,
                                                  const float* __restrict__ We,
                                                  const float* __restrict__ be,
                                                  const float* __restrict__ root,
                                                  const float* __restrict__ bias,
                                                  int o_total, int o_base,
                                                  int which_h, int h_stride) {
    extern __shared__ float sm_[];
    float* sh = sm_;                  // 8192 floats
    float* sw = sm_ + 8192;           // 2048 floats
    float* sb = sm_ + 8192 + 2048;    // 32 floats

    int tid = threadIdx.x;
    int n0 = blockIdx.x * 256;
    const float* hin = hin_sel ? g_h1 : xin;
    int lane = tid & 31, wrp = tid >> 5;

    // stage h transposed [f][n]
#pragma unroll
    for (int it = 0; it < 8; ++it) {
        int n = it * 32 + lane;
        int gn = n0 + n;
        float4 v = make_float4(0.f, 0.f, 0.f, 0.f);
        if (gn < N_ATOMS) v = *(const float4*)(hin + (size_t)gn * 32 + wrp * 4);
        if (relu) {
            v.x = fmaxf(v.x, 0.f); v.y = fmaxf(v.y, 0.f);
            v.z = fmaxf(v.z, 0.f); v.w = fmaxf(v.w, 0.f);
        }
        sh[(wrp * 4 + 0) * 256 + n] = v.x;
        sh[(wrp * 4 + 1) * 256 + n] = v.y;
        sh[(wrp * 4 + 2) * 256 + n] = v.z;
        sh[(wrp * 4 + 3) * 256 + n] = v.w;
    }
    if (tid < 32) sb[tid] = bias[o_base + tid];

    int tx = tid & 7;     // 8 cols
    int ty = tid >> 3;    // 8-node group (4 pairs)

    for (int ct3 = 0; ct3 < 3; ++ct3) {
        int ct = blockIdx.y * 3 + ct3;
        __syncthreads();  // prior tile reads (and initial h staging) complete
        // stage weights (natural layout) for this 64-col tile
        for (int i = tid; i < 2048; i += 256) {
            int f = i >> 6, cc = i & 63;
            int c = ct * 64 + cc;
            int d = c >> 5, o = c & 31;
            float v;
            if (d < 16)       v = We[(d * 32 + f) * o_total + o_base + o];
            else if (d == 16) v = be[f * o_total + o_base + o];
            else              v = root[f * o_total + o_base + o];
            sw[f * 64 + cc] = v;
        }
        __syncthreads();

        u64 acc[4][8];
#pragma unroll
        for (int p = 0; p < 4; ++p)
#pragma unroll
            for (int c = 0; c < 8; ++c) acc[p][c] = 0ull;

#pragma unroll 4
        for (int f = 0; f < 32; ++f) {
            const float* fb = sh + f * 256 + ty * 8;
            ulonglong2 hA = *(const ulonglong2*)(fb);       // pairs (n0,n1),(n2,n3)
            ulonglong2 hB = *(const ulonglong2*)(fb + 4);   // pairs (n4,n5),(n6,n7)
            const float* wb = sw + f * 64 + tx * 8;
            float4 wA = *(const float4*)(wb);               // c0..c3
            float4 wB = *(const float4*)(wb + 4);           // c4..c7
            u64 hh[4] = {hA.x, hA.y, hB.x, hB.y};
            u64 ww[8];
            ww[0] = pk2(wA.x, wA.x); ww[1] = pk2(wA.y, wA.y);
            ww[2] = pk2(wA.z, wA.z); ww[3] = pk2(wA.w, wA.w);
            ww[4] = pk2(wB.x, wB.x); ww[5] = pk2(wB.y, wB.y);
            ww[6] = pk2(wB.z, wB.z); ww[7] = pk2(wB.w, wB.w);
#pragma unroll
            for (int p = 0; p < 4; ++p)
#pragma unroll
                for (int c = 0; c < 8; ++c)
                    fma2(acc[p][c], hh[p], ww[c]);
        }

        int c0 = ct * 64 + tx * 8;
        int d = c0 >> 5, o0 = c0 & 31;
        int nb = n0 + ty * 8;
        if (d < 17) {
#pragma unroll
            for (int r = 0; r < 8; ++r) {
                int n = nb + r;
                if (n < N_ATOMS) {
                    int p = r >> 1;
                    float v[8];
#pragma unroll
                    for (int c = 0; c < 8; ++c) {
                        float2 t = up2(acc[p][c]);
                        v[c] = (r & 1) ? t.y : t.x;
                    }
                    float* yp = g_y + (size_t)n * YSTRIDE + d * 32 + o0;
                    *(float4*)(yp)     = make_float4(v[0], v[1], v[2], v[3]);
                    *(float4*)(yp + 4) = make_float4(v[4], v[5], v[6], v[7]);
                }
            }
        } else {
            float* hbase = (which_h == 1 ? g_h1 : g_h2);
#pragma unroll
            for (int r = 0; r < 8; ++r) {
                int n = nb + r;
                if (n < N_ATOMS) {
                    int p = r >> 1;
                    float v[8];
#pragma unroll
                    for (int c = 0; c < 8; ++c) {
                        float2 t = up2(acc[p][c]);
                        v[c] = ((r & 1) ? t.y : t.x) + sb[o0 + c];
                    }
                    float* hp = hbase + (size_t)n * h_stride + o_base + o0;
                    *(float4*)(hp)     = make_float4(v[0], v[1], v[2], v[3]);
                    *(float4*)(hp + 4) = make_float4(v[4], v[5], v[6], v[7]);
                }
            }
        }
    }
}

// ---------------- edge contraction ----------------
__global__ void __launch_bounds__(256) k_econ(const int* __restrict__ eidx,
                                              const float* __restrict__ ea_g,
                                              int which_h, int h_stride, int o_base) {
    int warp = threadIdx.x >> 5, lane = threadIdx.x & 31;
    int e = blockIdx.x * 8 + warp;
    int src = __ldg(eidx + e);
    int dst = __ldg(eidx + N_EDGES + e);
    float ead = (lane < 16) ? __ldg(ea_g + e * 16 + lane) : 1.0f;
    const float* yrow = g_y + (size_t)src * YSTRIDE + lane;
    float acc = 0.0f;
#pragma unroll
    for (int d = 0; d < 17; ++d) {
        float w = __shfl_sync(0xffffffffu, ead, d);
        acc = fmaf(w, __ldg(yrow + d * 32), acc);
    }
    float* hp = (which_h == 1 ? g_h1 : g_h2) + (size_t)dst * h_stride + o_base + lane;
    red1(hp, acc);
}

// ---------------- atom attention readout ----------------
__global__ void __launch_bounds__(128) k_attn(const int* __restrict__ labels,
                                              const float* __restrict__ wa_g,
                                              const float* __restrict__ ba_g) {
    extern __shared__ float sm[];
    float* sc = sm;
    float* wa = sm + 1000;
    float* red = sm + 1064;
    float* wacc = sm + 1192;

    int b = blockIdx.x, tid = threadIdx.x;
    const float* h2b = g_h2 + (size_t)b * NPG * H2D;
    if (tid < 64) wa[tid] = wa_g[tid];
    for (int i = tid; i < 4 * M_M * H2D; i += 128) wacc[i] = 0.0f;
    for (int i = tid; i < M_M * G_DIM; i += 128) g_gg[b * M_M * G_DIM + i] = 0.0f;
    __syncthreads();

    float ba = ba_g[0];
    for (int i = tid; i < NPG; i += 128) {
        const float4* r4 = (const float4*)(h2b + i * H2D);
        float s = ba;
#pragma unroll
        for (int o4 = 0; o4 < 16; ++o4) {
            float4 v = r4[o4];
            s = fmaf(fmaxf(v.x, 0.0f), wa[o4 * 4 + 0], s);
            s = fmaf(fmaxf(v.y, 0.0f), wa[o4 * 4 + 1], s);
            s = fmaf(fmaxf(v.z, 0.0f), wa[o4 * 4 + 2], s);
            s = fmaf(fmaxf(v.w, 0.0f), wa[o4 * 4 + 3], s);
        }
        sc[i] = s;
    }
    __syncthreads();
    float mx = -1e30f;
    for (int i = tid; i < NPG; i += 128) mx = fmaxf(mx, sc[i]);
    red[tid] = mx;
    __syncthreads();
    for (int s = 64; s > 0; s >>= 1) {
        if (tid < s) red[tid] = fmaxf(red[tid], red[tid + s]);
        __syncthreads();
    }
    mx = red[0];
    __syncthreads();
    float se = 0.0f;
    for (int i = tid; i < NPG; i += 128) {
        float e2 = expf(sc[i] - mx);
        sc[i] = e2;
        se += e2;
    }
    red[tid] = se;
    __syncthreads();
    for (int s = 64; s > 0; s >>= 1) {
        if (tid < s) red[tid] += red[tid + s];
        __syncthreads();
    }
    float inv = 1.0f / red[0];
    __syncthreads();

    int w = tid >> 5, lane = tid & 31;
    float* wp = wacc + w * (M_M * H2D);
    for (int i = w; i < NPG; i += 4) {
        int m = labels[b * NPG + i];
        float c = sc[i] * inv;
        const float* row = h2b + i * H2D;
        wp[m * H2D + lane]      += c * fmaxf(row[lane], 0.0f);
        wp[m * H2D + 32 + lane] += c * fmaxf(row[32 + lane], 0.0f);
    }
    __syncthreads();
    for (int i = tid; i < M_M * H2D; i += 128) {
        g_aa[b * M_M * H2D + i] =
            wacc[i] + wacc[3200 + i] + wacc[6400 + i] + wacc[9600 + i];
    }
}

// ---------------- ARMA (float4 x loads, f32x2) ----------------
__device__ __forceinline__ void arma_mm2(u64 acc2[5][2], const float* __restrict__ xs,
                                         int xstride, int F,
                                         const float* __restrict__ ws, int m0, int o0) {
    const float* x0p = xs + m0 * xstride;
    const float* x1p = x0p + xstride;
    const float* x2p = x1p + xstride;
    const float* x3p = x2p + xstride;
    const float* x4p = x3p + xstride;
    const float* wp = ws + o0;
#pragma unroll 2
    for (int f = 0; f < F; f += 4) {
        float4 a0 = *(const float4*)(x0p + f);
        float4 a1 = *(const float4*)(x1p + f);
        float4 a2 = *(const float4*)(x2p + f);
        float4 a3 = *(const float4*)(x3p + f);
        float4 a4 = *(const float4*)(x4p + f);
        float xa[5][4] = {
            {a0.x, a0.y, a0.z, a0.w},
            {a1.x, a1.y, a1.z, a1.w},
            {a2.x, a2.y, a2.z, a2.w},
            {a3.x, a3.y, a3.z, a3.w},
            {a4.x, a4.y, a4.z, a4.w}};
#pragma unroll
        for (int j = 0; j < 4; ++j) {
            ulonglong2 wv = *(const ulonglong2*)(wp + (f + j) * G_DIM);
#pragma unroll
            for (int r = 0; r < 5; ++r) {
                u64 xv = pk2(xa[r][j], xa[r][j]);
                fma2(acc2[r][0], xv, wv.x);
                fma2(acc2[r][1], xv, wv.y);
            }
        }
    }
}

__device__ __forceinline__ void stage_w(float* dstS, const float* __restrict__ src,
                                        int n4, int tid) {
    const float4* s4 = (const float4*)src;
    float4* d4 = (float4*)dstS;
    for (int i = tid; i < n4; i += 320) d4[i] = s4[i];
}

// smem floats: x0s[8000] | bufA[6400] | bufB[6400] | ws[20480] (at 20800)
__global__ void __launch_bounds__(320) k_arma(const float* __restrict__ aaf,
                                              const float* __restrict__ w_init,
                                              const float* __restrict__ w_mid,
                                              const float* __restrict__ w_root,
                                              const float* __restrict__ w_bias) {
    extern __shared__ float sm[];
    float* x0s = sm;
    float* bufA = sm + 8000;
    float* bufB = sm + 14400;
    float* ws = sm + 20800;

    int b = blockIdx.x / K_S, k = blockIdx.x % K_S;
    int tid = threadIdx.x;
    for (int i = tid; i < M_M * X0PAD; i += 320) {
        int m = i / X0PAD, f = i % X0PAD;
        float v = 0.0f;
        if (f < H2D)        v = g_aa[(b * M_M + m) * H2D + f];
        else if (f < X0DIM) v = aaf[(b * M_M + m) * AAF + (f - H2D)];
        x0s[m * X0PAD + f] = v;
    }
    for (int i = tid; i < G_DIM; i += 320) ws[X0DIM * G_DIM + i] = 0.0f;
    stage_w(ws, w_init + (size_t)k * X0DIM * G_DIM, X0DIM * G_DIM / 4, tid);
    __syncthreads();

    int warp = tid >> 5, lane = tid & 31;
    int m0 = warp * 5, o0 = lane * 4;
    u64 acc2[5][2];

#pragma unroll
    for (int mi = 0; mi < 5; ++mi) { acc2[mi][0] = 0ull; acc2[mi][1] = 0ull; }
    arma_mm2(acc2, x0s, X0PAD, X0PAD, ws, m0, o0);
#pragma unroll
    for (int mi = 0; mi < 5; ++mi) {
        ulonglong2 v; v.x = acc2[mi][0]; v.y = acc2[mi][1];
        *(ulonglong2*)(bufA + (m0 + mi) * G_DIM + o0) = v;
    }
    __syncthreads();

    float accf[5][4];
    for (int t = 0; t < T_L; ++t) {
        const float* cur = bufA;
        if (t > 0) {
            stage_w(ws, w_mid + (size_t)((t - 1) * K_S + k) * G_DIM * G_DIM,
                    G_DIM * G_DIM / 4, tid);
            __syncthreads();
#pragma unroll
            for (int mi = 0; mi < 5; ++mi) { acc2[mi][0] = 0ull; acc2[mi][1] = 0ull; }
            arma_mm2(acc2, bufA, G_DIM, G_DIM, ws, m0, o0);
#pragma unroll
            for (int mi = 0; mi < 5; ++mi) {
                ulonglong2 v; v.x = acc2[mi][0]; v.y = acc2[mi][1];
                *(ulonglong2*)(bufB + (m0 + mi) * G_DIM + o0) = v;
            }
            __syncthreads();
            cur = bufB;
        }
        stage_w(ws, w_root + (size_t)(t * K_S + k) * X0DIM * G_DIM,
                X0DIM * G_DIM / 4, tid);
        __syncthreads();
#pragma unroll
        for (int mi = 0; mi < 5; ++mi) { acc2[mi][0] = 0ull; acc2[mi][1] = 0ull; }
        arma_mm2(acc2, x0s, X0PAD, X0PAD, ws, m0, o0);
#pragma unroll
        for (int mi = 0; mi < 5; ++mi) {
            int m = m0 + mi;
            int e0 = g_aoff[m], e1 = g_aoff[m + 1];
            for (int e = e0; e < e1; ++e) {
                int s = g_asrc[e];
                u64 nr2 = pk2(g_anorm[e], g_anorm[e]);
                ulonglong2 cv = *(const ulonglong2*)(cur + s * G_DIM + o0);
                fma2(acc2[mi][0], nr2, cv.x);
                fma2(acc2[mi][1], nr2, cv.y);
            }
        }
        ulonglong2 bv = *(const ulonglong2*)(w_bias + (t * K_S + k) * G_DIM + o0);
#pragma unroll
        for (int mi = 0; mi < 5; ++mi) {
            add2(acc2[mi][0], bv.x);
            add2(acc2[mi][1], bv.y);
            float2 lo = up2(acc2[mi][0]), hi = up2(acc2[mi][1]);
            accf[mi][0] = fmaxf(lo.x, 0.0f); accf[mi][1] = fmaxf(lo.y, 0.0f);
            accf[mi][2] = fmaxf(hi.x, 0.0f); accf[mi][3] = fmaxf(hi.y, 0.0f);
        }
        __syncthreads();
#pragma unroll
        for (int mi = 0; mi < 5; ++mi)
            *(float4*)(bufA + (m0 + mi) * G_DIM + o0) =
                make_float4(accf[mi][0], accf[mi][1], accf[mi][2], accf[mi][3]);
        __syncthreads();
    }
    const float invK = 1.0f / (float)K_S;
#pragma unroll
    for (int mi = 0; mi < 5; ++mi)
        red4(&g_gg[b * M_M * G_DIM + (m0 + mi) * G_DIM + o0],
             accf[mi][0] * invK, accf[mi][1] * invK,
             accf[mi][2] * invK, accf[mi][3] * invK);
}

// ---------------- amino attention + MLP head ----------------
__global__ void __launch_bounds__(128) k_final(const float* __restrict__ waa,
                                               const float* __restrict__ baa,
                                               const float* __restrict__ W1,
                                               const float* __restrict__ b1,
                                               const float* __restrict__ W2,
                                               const float* __restrict__ b2,
                                               const float* __restrict__ W3,
                                               const float* __restrict__ b3,
                                               const float* __restrict__ W4,
                                               const float* __restrict__ b4,
                                               float* __restrict__ out) {
    __shared__ float gs[M_M * G_DIM];
    __shared__ float sc[M_M];
    __shared__ float p[G_DIM];
    __shared__ float f1[F1D];
    __shared__ float f2[F2D];
    __shared__ float f3[F3D];
    int b = blockIdx.x, tid = threadIdx.x;
    for (int i = tid; i < M_M * G_DIM; i += 128) gs[i] = g_gg[b * M_M * G_DIM + i];
    __syncthreads();
    if (tid < M_M) {
        float s = baa[0];
#pragma unroll 4
        for (int o = 0; o < G_DIM; ++o) s = fmaf(gs[tid * G_DIM + o], waa[o], s);
        sc[tid] = s;
    }
    __syncthreads();
    if (tid == 0) {
        float mx = -1e30f;
        for (int m = 0; m < M_M; ++m) mx = fmaxf(mx, sc[m]);
        float se = 0.0f;
        for (int m = 0; m < M_M; ++m) {
            float e = expf(sc[m] - mx);
            sc[m] = e;
            se += e;
        }
        float inv = 1.0f / se;
        for (int m = 0; m < M_M; ++m) sc[m] *= inv;
    }
    __syncthreads();
    {
        float pv = 0.0f;
        for (int m = 0; m < M_M; ++m) pv = fmaf(sc[m], gs[m * G_DIM + tid], pv);
        p[tid] = pv;
    }
    __syncthreads();
    if (tid < F1D) {
        float v = b1[tid];
        for (int i = 0; i < G_DIM; ++i) v = fmaf(p[i], W1[i * F1D + tid], v);
        f1[tid] = fmaxf(v, 0.0f);
    }
    __syncthreads();
    if (tid < F2D) {
        float v = b2[tid];
        for (int i = 0; i < F1D; ++i) v = fmaf(f1[i], W2[i * F2D + tid], v);
        f2[tid] = fmaxf(v, 0.0f);
    }
    __syncthreads();
    if (tid < F3D) {
        float v = b3[tid];
        for (int i = 0; i < F2D; ++i) v = fmaf(f2[i], W3[i * F3D + tid], v);
        f3[tid] = fmaxf(v, 0.0f);
    }
    __syncthreads();
    if (tid == 0) {
        float v = b4[0];
        for (int i = 0; i < F3D; ++i) v = fmaf(f3[i], W4[i], v);
        out[b] = v;
    }
}

// ---------------- launch ----------------
extern "C" void kernel_launch(void* const* d_in, const int* in_sizes, int n_in,
                              void* d_out, int out_size) {
    const float* x              = (const float*)d_in[0];
    const float* edge_attr      = (const float*)d_in[1];
    const float* aa_features    = (const float*)d_in[2];
    const int*   edge_index     = (const int*)d_in[3];
    const int*   monomer_labels = (const int*)d_in[4];
    const int*   amino_edge_idx = (const int*)d_in[5];
    const float* W_e1   = (const float*)d_in[6];
    const float* b_e1   = (const float*)d_in[7];
    const float* root1  = (const float*)d_in[8];
    const float* bias1  = (const float*)d_in[9];
    const float* W_e2   = (const float*)d_in[10];
    const float* b_e2   = (const float*)d_in[11];
    const float* root2  = (const float*)d_in[12];
    const float* bias2  = (const float*)d_in[13];
    const float* Wa_atom = (const float*)d_in[14];
    const float* ba_atom = (const float*)d_in[15];
    const float* arma_init_w = (const float*)d_in[16];
    const float* arma_w      = (const float*)d_in[17];
    const float* arma_root_w = (const float*)d_in[18];
    const float* arma_bias   = (const float*)d_in[19];
    const float* Wa_aa = (const float*)d_in[20];
    const float* ba_aa = (const float*)d_in[21];
    const float* W1 = (const float*)d_in[22];
    const float* b1 = (const float*)d_in[23];
    const float* W2 = (const float*)d_in[24];
    const float* b2 = (const float*)d_in[25];
    const float* W3 = (const float*)d_in[26];
    const float* b3 = (const float*)d_in[27];
    const float* W4 = (const float*)d_in[28];
    const float* b4 = (const float*)d_in[29];
    float* out = (float*)d_out;

    const int YG_SMEM   = (8192 + 2048 + 32) * 4;            // 41088 B
    const int ATTN_SMEM = (1000 + 64 + 128 + 12800) * 4;     // 55968 B
    const int ARMA_SMEM = (20800 + 20480) * 4;               // 165120 B
    cudaFuncSetAttribute(k_ygemm, cudaFuncAttributeMaxDynamicSharedMemorySize, YG_SMEM);
    cudaFuncSetAttribute(k_attn, cudaFuncAttributeMaxDynamicSharedMemorySize, ATTN_SMEM);
    cudaFuncSetAttribute(k_arma, cudaFuncAttributeMaxDynamicSharedMemorySize, ARMA_SMEM);

    dim3 YG_GRID((N_ATOMS + 255) / 256, 3);      // 196 x 3 (3 col-tiles each)
    const int ECON_GRID = N_EDGES / 8;           // 12500

    k_amino_prep<<<1, 32>>>(amino_edge_idx);

    // conv1
    k_ygemm<<<YG_GRID, 256, YG_SMEM>>>(x, 0, 0, W_e1, b_e1, root1, bias1, 32, 0, 1, H1D);
    k_econ<<<ECON_GRID, 256>>>(edge_index, edge_attr, 1, H1D, 0);

    // conv2 half 0 (outputs 0..31)
    k_ygemm<<<YG_GRID, 256, YG_SMEM>>>(x, 1, 1, W_e2, b_e2, root2, bias2, 64, 0, 2, H2D);
    k_econ<<<ECON_GRID, 256>>>(edge_index, edge_attr, 2, H2D, 0);

    // conv2 half 1 (outputs 32..63)
    k_ygemm<<<YG_GRID, 256, YG_SMEM>>>(x, 1, 1, W_e2, b_e2, root2, bias2, 64, 32, 2, H2D);
    k_econ<<<ECON_GRID, 256>>>(edge_index, edge_attr, 2, H2D, 32);

    k_attn<<<B_G, 128, ATTN_SMEM>>>(monomer_labels, Wa_atom, ba_atom);
    k_arma<<<B_G * K_S, 320, ARMA_SMEM>>>(aa_features, arma_init_w, arma_w, arma_root_w, arma_bias);
    k_final<<<B_G, 128>>>(Wa_aa, ba_aa, W1, b1, W2, b2, W3, b3, W4, b4, out);
}